// round 9
// baseline (speedup 1.0000x reference)
#include <cuda_runtime.h>
#include <cuda_fp16.h>
#include <cstdint>

#define Bv 2
#define Sv 2048
#define Dv 1024
#define Hv 16
#define HDv 64
#define FFv 4096
#define Ev 8
#define NTOK (Bv*Sv)          // 4096
#define MAXP 10240            // 2*NTOK + 8*256 padding (256-aligned segments)
#define LNEPS 1e-5f

// ---------------- scratch (device globals; no runtime alloc) ----------------
__device__ __half g_xh[(size_t)NTOK * Dv];
__device__ __half g_qkvh[(size_t)NTOK * 3 * Dv];
__device__ __half g_ctxh[(size_t)NTOK * Dv];
__device__ __half g_xgh[(size_t)MAXP * Dv];
__device__ __half g_hh[(size_t)MAXP * FFv];
__device__ __half g_inwh[(size_t)3 * Dv * Dv];
__device__ __half g_outwh[(size_t)Dv * Dv];
__device__ __half g_w1h[(size_t)Ev * FFv * Dv];
__device__ __half g_w2h[(size_t)Ev * Dv * FFv];
__device__ float g_attnout[(size_t)NTOK * Dv];
__device__ float g_x1[(size_t)NTOK * Dv];
__device__ float g_eo[(size_t)MAXP * Dv];
__device__ float g_logits[(size_t)NTOK * Ev];
__device__ float g_topw[(size_t)NTOK * 2];
__device__ int   g_topE[(size_t)NTOK * 2];
__device__ int   g_pos[(size_t)NTOK * 2];
__device__ int   g_counts[Ev];
__device__ int   g_cursor[Ev];
__device__ int   g_off[Ev + 1];
__device__ int   g_Mpad[1];
__device__ int   g_gather[MAXP];

// ======================= PTX helpers =======================
__device__ __forceinline__ unsigned smem_u32(const void* p) {
    unsigned a;
    asm("{ .reg .u64 t; cvta.to.shared.u64 t, %1; cvt.u32.u64 %0, t; }" : "=r"(a) : "l"(p));
    return a;
}
__device__ __forceinline__ void cpa16(unsigned dst, const void* src) {
    asm volatile("cp.async.cg.shared.global [%0], [%1], 16;" :: "r"(dst), "l"(src));
}
__device__ __forceinline__ void ldsm_x4(unsigned& r0, unsigned& r1, unsigned& r2, unsigned& r3, unsigned a) {
    asm volatile("ldmatrix.sync.aligned.m8n8.x4.shared.b16 {%0,%1,%2,%3}, [%4];"
        : "=r"(r0), "=r"(r1), "=r"(r2), "=r"(r3) : "r"(a));
}
__device__ __forceinline__ void ldsm_x2t(unsigned& r0, unsigned& r1, unsigned a) {
    asm volatile("ldmatrix.sync.aligned.m8n8.x2.trans.shared.b16 {%0,%1}, [%2];"
        : "=r"(r0), "=r"(r1) : "r"(a));
}
__device__ __forceinline__ void mma_f16(float* c,
    unsigned a0, unsigned a1, unsigned a2, unsigned a3, unsigned b0, unsigned b1)
{
    asm volatile(
        "mma.sync.aligned.m16n8k16.row.col.f32.f16.f16.f32 "
        "{%0,%1,%2,%3}, {%4,%5,%6,%7}, {%8,%9}, {%0,%1,%2,%3};"
        : "+f"(c[0]), "+f"(c[1]), "+f"(c[2]), "+f"(c[3])
        : "r"(a0), "r"(a1), "r"(a2), "r"(a3), "r"(b0), "r"(b1));
}
__device__ __forceinline__ unsigned pack_h2(float a, float b) {
    __half2 h = __floats2half2_rn(a, b);
    return *reinterpret_cast<unsigned*>(&h);
}

extern __shared__ float smem_f[];

// ======================= fp32 -> fp16 converter =======================
__global__ __launch_bounds__(256) void k_f2h(const float4* __restrict__ in,
                                             __half2* __restrict__ out, int n4)
{
    int i = blockIdx.x * blockDim.x + threadIdx.x;
    if (i >= n4) return;
    float4 v = in[i];
    out[2 * i]     = __floats2half2_rn(v.x, v.y);
    out[2 * i + 1] = __floats2half2_rn(v.z, v.w);
}

// ======================= fp16 mma GEMM =======================
// C[M,N] = A[M,K]h * B[N,K]h^T + bias. 256x128 CTA tile, K-tile 32, 4 stages,
// single __syncthreads per k-iter. 256 threads: 8 warps (4m x 2n), 64x64 each.
#define GSTR 40                         // smem row stride in halfs (80B)
#define A_TILE_H (256 * GSTR)           // 10240 halfs
#define B_TILE_H (128 * GSTR)           // 5120 halfs
#define GSTAGE_H (A_TILE_H + B_TILE_H)  // 15360 halfs per stage
#define NST 4
#define GSMEMH (NST * GSTAGE_H * 2)     // 122880 bytes

__device__ __forceinline__ void load_tile_h(unsigned sBase,
    const __half* __restrict__ A, int lda, const __half* __restrict__ Bm, int ldb,
    int row0, int col0, int k0, int tid)
{
    #pragma unroll
    for (int i = 0; i < 4; i++) {
        int idx = i * 256 + tid;
        int r = idx >> 2, c = idx & 3;
        unsigned doff = (unsigned)((r * GSTR + c * 8) * 2);
        cpa16(sBase + doff, A + (long)(row0 + r) * lda + k0 + c * 8);
    }
    #pragma unroll
    for (int i = 0; i < 2; i++) {
        int idx = i * 256 + tid;
        int r = idx >> 2, c = idx & 3;
        unsigned doff = (unsigned)((r * GSTR + c * 8) * 2);
        cpa16(sBase + A_TILE_H * 2 + doff, Bm + (long)(col0 + r) * ldb + k0 + c * 8);
    }
}

__global__ __launch_bounds__(256, 1) void gemm_h(
    const __half* __restrict__ A, const __half* __restrict__ Bm,
    const float* __restrict__ bias, float* __restrict__ C, __half* __restrict__ Ch,
    int Kd, int lda, int ldb, int ldc,
    const int* __restrict__ dM, const int* __restrict__ exp_off,
    long bStride, int biasStride, int relu)
{
    int row0 = blockIdx.y * 256;
    if (dM && row0 >= *dM) return;
    int col0 = blockIdx.x * 128;
    if (exp_off) {
        int e = 0;
        while (row0 >= exp_off[e + 1]) e++;
        Bm += (long)e * bStride;
        bias += (long)e * biasStride;
    }
    int tid = threadIdx.x, lane = tid & 31, wid = tid >> 5;
    int warp_m = wid >> 1, warp_n = wid & 1;
    unsigned sb = smem_u32(smem_f);

    float acc[4][8][4];
    #pragma unroll
    for (int mt = 0; mt < 4; mt++)
        #pragma unroll
        for (int nt = 0; nt < 8; nt++)
            #pragma unroll
            for (int j = 0; j < 4; j++) acc[mt][nt][j] = 0.f;

    int nK = Kd / 32;
    #pragma unroll
    for (int s = 0; s < 3; s++) {
        load_tile_h(sb + s * GSTAGE_H * 2, A, lda, Bm, ldb, row0, col0, s * 32, tid);
        asm volatile("cp.async.commit_group;" ::: "memory");
    }

    // ldmatrix per-lane addressing
    int arow = lane & 15, akb = lane >> 4;
    int bnrow = (lane & 7) + ((lane >> 4) & 1) * 8;
    int bkb = (lane >> 3) & 1;

    for (int kt = 0; kt < nK; kt++) {
        asm volatile("cp.async.wait_group 2;" ::: "memory");
        __syncthreads();
        if (kt + 3 < nK)
            load_tile_h(sb + ((kt + 3) & 3) * GSTAGE_H * 2, A, lda, Bm, ldb, row0, col0, (kt + 3) * 32, tid);
        asm volatile("cp.async.commit_group;" ::: "memory");

        unsigned sA = sb + (kt & 3) * GSTAGE_H * 2;
        unsigned sB = sA + A_TILE_H * 2;

        #pragma unroll
        for (int ks = 0; ks < 2; ks++) {
            unsigned af[4][4], bf[4][4];
            #pragma unroll
            for (int mt = 0; mt < 4; mt++) {
                unsigned addr = sA + (unsigned)(((warp_m * 64 + mt * 16 + arow) * GSTR
                                 + ks * 16 + akb * 8) * 2);
                ldsm_x4(af[mt][0], af[mt][1], af[mt][2], af[mt][3], addr);
            }
            #pragma unroll
            for (int nt2 = 0; nt2 < 4; nt2++) {
                unsigned addr = sB + (unsigned)(((warp_n * 64 + nt2 * 16 + bnrow) * GSTR
                                 + ks * 16 + bkb * 8) * 2);
                ldsm_x4(bf[nt2][0], bf[nt2][1], bf[nt2][2], bf[nt2][3], addr);
            }
            #pragma unroll
            for (int mt = 0; mt < 4; mt++)
                #pragma unroll
                for (int nt2 = 0; nt2 < 4; nt2++) {
                    mma_f16(acc[mt][2 * nt2],     af[mt][0], af[mt][1], af[mt][2], af[mt][3],
                            bf[nt2][0], bf[nt2][1]);
                    mma_f16(acc[mt][2 * nt2 + 1], af[mt][0], af[mt][1], af[mt][2], af[mt][3],
                            bf[nt2][2], bf[nt2][3]);
                }
        }
    }

    int g = lane >> 2, j = lane & 3;
    #pragma unroll
    for (int mt = 0; mt < 4; mt++) {
        int r = row0 + warp_m * 64 + mt * 16 + g;
        #pragma unroll
        for (int nt = 0; nt < 8; nt++) {
            int cg = col0 + warp_n * 64 + nt * 8 + j * 2;
            float b0 = bias[cg], b1 = bias[cg + 1];
            float v0 = acc[mt][nt][0] + b0, v1 = acc[mt][nt][1] + b1;
            float v2 = acc[mt][nt][2] + b0, v3 = acc[mt][nt][3] + b1;
            if (relu) {
                v0 = fmaxf(v0, 0.f); v1 = fmaxf(v1, 0.f);
                v2 = fmaxf(v2, 0.f); v3 = fmaxf(v3, 0.f);
            }
            if (Ch) {
                *(__half2*)(Ch + (long)r * ldc + cg) = __floats2half2_rn(v0, v1);
                *(__half2*)(Ch + (long)(r + 8) * ldc + cg) = __floats2half2_rn(v2, v3);
            } else {
                *(float2*)(C + (long)r * ldc + cg) = make_float2(v0, v1);
                *(float2*)(C + (long)(r + 8) * ldc + cg) = make_float2(v2, v3);
            }
        }
    }
}

// ======================= fp16 tensor-core flash attention =======================
// CTA: 128 queries (4 warps x 32 rows), 64-key tiles, double-buffered.
#define ASTR 72
#define AQ_OFF 0
#define AK_OFF (128 * ASTR)                 // 9216
#define AV_OFF (AK_OFF + 2 * 64 * ASTR)     // 18432
#define ASMEMH ((AV_OFF + 2 * 64 * ASTR) * 2)   // 55296 bytes

__global__ __launch_bounds__(128) void k_attn_h(const __half* __restrict__ qkv,
                                                __half* __restrict__ ctx)
{
    __half* sm = (__half*)smem_f;
    int tid = threadIdx.x, lane = tid & 31, wid = tid >> 5;
    int b = blockIdx.y >> 4, h = blockIdx.y & 15;
    int q0 = blockIdx.x * 128;
    const __half* base = qkv + (long)b * Sv * (3 * Dv) + h * HDv;
    unsigned sb = smem_u32(sm);
    int g = lane >> 2, j = lane & 3;
    int qb = wid * 32;
    int arow = lane & 15;
    int akb = lane >> 4;
    int l2 = lane & 15;

    #pragma unroll
    for (int i = 0; i < 8; i++) {
        int idx = i * 128 + tid;
        int r = idx >> 3, c = idx & 7;
        cpa16(sb + (unsigned)((AQ_OFF + r * ASTR + c * 8) * 2),
              base + (long)(q0 + r) * (3 * Dv) + c * 8);
    }
    #pragma unroll
    for (int i = 0; i < 4; i++) {
        int idx = i * 128 + tid;
        int r = idx >> 3, c = idx & 7;
        cpa16(sb + (unsigned)((AK_OFF + r * ASTR + c * 8) * 2), base + (long)r * (3 * Dv) + Dv + c * 8);
        cpa16(sb + (unsigned)((AV_OFF + r * ASTR + c * 8) * 2), base + (long)r * (3 * Dv) + 2 * Dv + c * 8);
    }
    asm volatile("cp.async.commit_group;" ::: "memory");
    asm volatile("cp.async.wait_group 0;" ::: "memory");
    __syncthreads();

    unsigned qf[2][4][4];
    #pragma unroll
    for (int mt = 0; mt < 2; mt++)
        #pragma unroll
        for (int ks = 0; ks < 4; ks++) {
            unsigned addr = sb + (unsigned)(((qb + mt * 16 + arow) * ASTR + ks * 16 + akb * 8) * 2);
            ldsm_x4(qf[mt][ks][0], qf[mt][ks][1], qf[mt][ks][2], qf[mt][ks][3], addr);
        }

    float Oa[2][8][4];
    float mrow[4], lrow[4];
    #pragma unroll
    for (int i = 0; i < 4; i++) { mrow[i] = -1e30f; lrow[i] = 0.f; }
    #pragma unroll
    for (int mt = 0; mt < 2; mt++)
        #pragma unroll
        for (int nt = 0; nt < 8; nt++)
            #pragma unroll
            for (int q = 0; q < 4; q++) Oa[mt][nt][q] = 0.f;

    for (int kt = 0; kt < Sv / 64; kt++) {
        int st = kt & 1;
        if (kt + 1 < Sv / 64) {
            int st2 = (kt + 1) & 1;
            #pragma unroll
            for (int i = 0; i < 4; i++) {
                int idx = i * 128 + tid;
                int r = idx >> 3, c = idx & 7;
                long gr = (long)((kt + 1) * 64 + r) * (3 * Dv);
                cpa16(sb + (unsigned)((AK_OFF + st2 * 64 * ASTR + r * ASTR + c * 8) * 2), base + gr + Dv + c * 8);
                cpa16(sb + (unsigned)((AV_OFF + st2 * 64 * ASTR + r * ASTR + c * 8) * 2), base + gr + 2 * Dv + c * 8);
            }
            asm volatile("cp.async.commit_group;" ::: "memory");
            asm volatile("cp.async.wait_group 1;" ::: "memory");
        } else {
            asm volatile("cp.async.wait_group 0;" ::: "memory");
        }
        __syncthreads();

        unsigned sK = sb + (unsigned)((AK_OFF + st * 64 * ASTR) * 2);
        unsigned sV = sb + (unsigned)((AV_OFF + st * 64 * ASTR) * 2);

        float sacc[2][8][4];
        #pragma unroll
        for (int mt = 0; mt < 2; mt++)
            #pragma unroll
            for (int nt = 0; nt < 8; nt++)
                #pragma unroll
                for (int q = 0; q < 4; q++) sacc[mt][nt][q] = 0.f;

        #pragma unroll
        for (int ks = 0; ks < 4; ks++) {
            unsigned bf[4][4];
            #pragma unroll
            for (int nt2 = 0; nt2 < 4; nt2++) {
                unsigned addr = sK + (unsigned)(((nt2 * 16 + (lane & 7) + ((lane >> 4) & 1) * 8) * ASTR
                                 + ks * 16 + ((lane >> 3) & 1) * 8) * 2);
                ldsm_x4(bf[nt2][0], bf[nt2][1], bf[nt2][2], bf[nt2][3], addr);
            }
            #pragma unroll
            for (int mt = 0; mt < 2; mt++)
                #pragma unroll
                for (int nt2 = 0; nt2 < 4; nt2++) {
                    mma_f16(sacc[mt][2 * nt2],     qf[mt][ks][0], qf[mt][ks][1], qf[mt][ks][2], qf[mt][ks][3],
                            bf[nt2][0], bf[nt2][1]);
                    mma_f16(sacc[mt][2 * nt2 + 1], qf[mt][ks][0], qf[mt][ks][1], qf[mt][ks][2], qf[mt][ks][3],
                            bf[nt2][2], bf[nt2][3]);
                }
        }

        #pragma unroll
        for (int mt = 0; mt < 2; mt++)
            #pragma unroll
            for (int hh = 0; hh < 2; hh++) {
                int ri = mt * 2 + hh;
                float rmax = -1e30f;
                #pragma unroll
                for (int nt = 0; nt < 8; nt++) {
                    float v0 = sacc[mt][nt][hh * 2] * 0.125f;
                    float v1 = sacc[mt][nt][hh * 2 + 1] * 0.125f;
                    sacc[mt][nt][hh * 2] = v0; sacc[mt][nt][hh * 2 + 1] = v1;
                    rmax = fmaxf(rmax, fmaxf(v0, v1));
                }
                rmax = fmaxf(rmax, __shfl_xor_sync(0xffffffffu, rmax, 1));
                rmax = fmaxf(rmax, __shfl_xor_sync(0xffffffffu, rmax, 2));
                float mnew = fmaxf(mrow[ri], rmax);
                float corr = __expf(mrow[ri] - mnew);
                mrow[ri] = mnew;
                float ps = 0.f;
                #pragma unroll
                for (int nt = 0; nt < 8; nt++) {
                    float p0 = __expf(sacc[mt][nt][hh * 2] - mnew);
                    float p1 = __expf(sacc[mt][nt][hh * 2 + 1] - mnew);
                    sacc[mt][nt][hh * 2] = p0; sacc[mt][nt][hh * 2 + 1] = p1;
                    ps += p0 + p1;
                }
                ps += __shfl_xor_sync(0xffffffffu, ps, 1);
                ps += __shfl_xor_sync(0xffffffffu, ps, 2);
                lrow[ri] = lrow[ri] * corr + ps;
                #pragma unroll
                for (int nt = 0; nt < 8; nt++) {
                    Oa[mt][nt][hh * 2] *= corr;
                    Oa[mt][nt][hh * 2 + 1] *= corr;
                }
            }

        #pragma unroll
        for (int ks = 0; ks < 4; ks++) {
            unsigned pa[2][4];
            #pragma unroll
            for (int mt = 0; mt < 2; mt++) {
                pa[mt][0] = pack_h2(sacc[mt][2 * ks][0],     sacc[mt][2 * ks][1]);
                pa[mt][1] = pack_h2(sacc[mt][2 * ks][2],     sacc[mt][2 * ks][3]);
                pa[mt][2] = pack_h2(sacc[mt][2 * ks + 1][0], sacc[mt][2 * ks + 1][1]);
                pa[mt][3] = pack_h2(sacc[mt][2 * ks + 1][2], sacc[mt][2 * ks + 1][3]);
            }
            #pragma unroll
            for (int nt = 0; nt < 8; nt++) {
                unsigned vb0, vb1;
                unsigned addr = sV + (unsigned)(((ks * 16 + (l2 & 7) + (l2 >> 3) * 8) * ASTR + nt * 8) * 2);
                ldsm_x2t(vb0, vb1, addr);
                #pragma unroll
                for (int mt = 0; mt < 2; mt++)
                    mma_f16(Oa[mt][nt], pa[mt][0], pa[mt][1], pa[mt][2], pa[mt][3], vb0, vb1);
            }
        }
        __syncthreads();
    }

    #pragma unroll
    for (int mt = 0; mt < 2; mt++)
        #pragma unroll
        for (int hh = 0; hh < 2; hh++) {
            float inv = 1.f / lrow[mt * 2 + hh];
            int qrow = q0 + qb + mt * 16 + g + hh * 8;
            __half* op = ctx + ((long)(b * Sv) + qrow) * Dv + h * HDv;
            #pragma unroll
            for (int nt = 0; nt < 8; nt++) {
                *(__half2*)(op + nt * 8 + 2 * j) =
                    __floats2half2_rn(Oa[mt][nt][hh * 2] * inv, Oa[mt][nt][hh * 2 + 1] * inv);
            }
        }
}

// ======================= small kernels =======================
__global__ void k_init() {
    int i = blockIdx.x * blockDim.x + threadIdx.x;
    if (i < MAXP) g_gather[i] = -1;
    if (i < Ev) g_counts[i] = 0;
}

// fused: x1 = LN1(x + attn_out); logits = x1 @ gw^T + gb; top-2 routing
__global__ __launch_bounds__(256) void k_addln_gate(const float* __restrict__ xa,
                                                    const float* __restrict__ xb,
                                                    const float* __restrict__ g,
                                                    const float* __restrict__ bt,
                                                    const float* __restrict__ gw,
                                                    const float* __restrict__ gb,
                                                    float* __restrict__ x1out)
{
    __shared__ float red[256];
    __shared__ float sm8[256 * Ev];
    int n = blockIdx.x, tid = threadIdx.x;
    const float* pa = xa + (long)n * Dv;
    const float* pb = xb + (long)n * Dv;
    float v[4]; float s = 0.f;
    #pragma unroll
    for (int i = 0; i < 4; i++) { int d = tid + i * 256; v[i] = pa[d] + pb[d]; s += v[i]; }
    red[tid] = s; __syncthreads();
    for (int st = 128; st > 0; st >>= 1) { if (tid < st) red[tid] += red[tid + st]; __syncthreads(); }
    float mean = red[0] * (1.f / Dv);
    __syncthreads();
    float vs = 0.f;
    #pragma unroll
    for (int i = 0; i < 4; i++) { float t = v[i] - mean; vs += t * t; }
    red[tid] = vs; __syncthreads();
    for (int st = 128; st > 0; st >>= 1) { if (tid < st) red[tid] += red[tid + st]; __syncthreads(); }
    float rstd = rsqrtf(red[0] * (1.f / Dv) + LNEPS);

    float p[Ev];
    #pragma unroll
    for (int e = 0; e < Ev; e++) p[e] = 0.f;
    #pragma unroll
    for (int i = 0; i < 4; i++) {
        int d = tid + i * 256;
        float xv = (v[i] - mean) * rstd * g[d] + bt[d];
        x1out[(long)n * Dv + d] = xv;
        #pragma unroll
        for (int e = 0; e < Ev; e++) p[e] += xv * gw[e * Dv + d];
    }
    #pragma unroll
    for (int e = 0; e < Ev; e++) sm8[tid * Ev + e] = p[e];
    __syncthreads();
    for (int st = 128; st > 0; st >>= 1) {
        if (tid < st)
            #pragma unroll
            for (int e = 0; e < Ev; e++) sm8[tid * Ev + e] += sm8[(tid + st) * Ev + e];
        __syncthreads();
    }
    if (tid == 0) {
        float l[Ev];
        #pragma unroll
        for (int e = 0; e < Ev; e++) { l[e] = sm8[e] + gb[e]; g_logits[(long)n * Ev + e] = l[e]; }
        int i0 = 0;
        #pragma unroll
        for (int e = 1; e < Ev; e++) if (l[e] > l[i0]) i0 = e;
        int i1 = -1;
        #pragma unroll
        for (int e = 0; e < Ev; e++) { if (e == i0) continue; if (i1 < 0 || l[e] > l[i1]) i1 = e; }
        float e1 = expf(l[i1] - l[i0]);
        float denom = 1.f + e1;
        g_topE[n * 2 + 0] = i0; g_topE[n * 2 + 1] = i1;
        g_topw[n * 2 + 0] = 1.f / denom; g_topw[n * 2 + 1] = e1 / denom;
        atomicAdd(&g_counts[i0], 1);
        atomicAdd(&g_counts[i1], 1);
    }
}

__global__ void k_scan() {
    if (threadIdx.x == 0) {
        int t = 0;
        for (int e = 0; e < Ev; e++) {
            g_off[e] = t; g_cursor[e] = t;
            t += (g_counts[e] + 255) & ~255;   // 256-aligned segments
        }
        g_off[Ev] = t;
        g_Mpad[0] = t;
    }
}

__global__ void k_assign() {
    int i = blockIdx.x * blockDim.x + threadIdx.x;
    if (i >= NTOK * 2) return;
    int e = g_topE[i];
    int p = atomicAdd(&g_cursor[e], 1);
    g_gather[p] = i >> 1;
    g_pos[i] = p;
}

__global__ __launch_bounds__(256) void k_gather(const float* __restrict__ x1,
                                                __half* __restrict__ xg)
{
    int p = blockIdx.x;
    int g = g_gather[p];
    __half2* dst = (__half2*)(xg + (long)p * Dv);
    int t = threadIdx.x;
    if (g >= 0) {
        float4 v = ((const float4*)(x1 + (long)g * Dv))[t];
        dst[2 * t]     = __floats2half2_rn(v.x, v.y);
        dst[2 * t + 1] = __floats2half2_rn(v.z, v.w);
    } else {
        dst[2 * t] = __floats2half2_rn(0.f, 0.f);
        dst[2 * t + 1] = __floats2half2_rn(0.f, 0.f);
    }
}

__global__ __launch_bounds__(256) void k_scatter_ln2(const float* __restrict__ x1,
                                                     const float* __restrict__ g,
                                                     const float* __restrict__ bt,
                                                     float* __restrict__ out)
{
    __shared__ float red[256];
    int n = blockIdx.x, tid = threadIdx.x;
    int p0 = g_pos[n * 2 + 0], p1 = g_pos[n * 2 + 1];
    float w0 = g_topw[n * 2 + 0], w1 = g_topw[n * 2 + 1];
    const float* px = x1 + (long)n * Dv;
    const float* pe0 = g_eo + (long)p0 * Dv;
    const float* pe1 = g_eo + (long)p1 * Dv;
    float v[4]; float s = 0.f;
    #pragma unroll
    for (int i = 0; i < 4; i++) {
        int d = tid + i * 256;
        v[i] = px[d] + w0 * pe0[d] + w1 * pe1[d];
        s += v[i];
    }
    red[tid] = s; __syncthreads();
    for (int st = 128; st > 0; st >>= 1) { if (tid < st) red[tid] += red[tid + st]; __syncthreads(); }
    float mean = red[0] * (1.f / Dv);
    __syncthreads();
    float vs = 0.f;
    #pragma unroll
    for (int i = 0; i < 4; i++) { float t = v[i] - mean; vs += t * t; }
    red[tid] = vs; __syncthreads();
    for (int st = 128; st > 0; st >>= 1) { if (tid < st) red[tid] += red[tid + st]; __syncthreads(); }
    float rstd = rsqrtf(red[0] * (1.f / Dv) + LNEPS);
    #pragma unroll
    for (int i = 0; i < 4; i++) {
        int d = tid + i * 256;
        out[(long)n * Dv + d] = (v[i] - mean) * rstd * g[d] + bt[d];
    }
}

__global__ __launch_bounds__(256) void k_lb(float* __restrict__ out) {
    __shared__ float sm[256][Ev];
    int tid = threadIdx.x;
    float u[Ev];
    #pragma unroll
    for (int e = 0; e < Ev; e++) u[e] = 0.f;
    for (int n = tid; n < NTOK; n += 256) {
        float l[Ev], mx = -1e30f, s = 0.f;
        #pragma unroll
        for (int e = 0; e < Ev; e++) { l[e] = g_logits[(long)n * Ev + e]; mx = fmaxf(mx, l[e]); }
        #pragma unroll
        for (int e = 0; e < Ev; e++) { l[e] = expf(l[e] - mx); s += l[e]; }
        float inv = 1.f / s;
        #pragma unroll
        for (int e = 0; e < Ev; e++) u[e] += l[e] * inv;
    }
    #pragma unroll
    for (int e = 0; e < Ev; e++) sm[tid][e] = u[e];
    __syncthreads();
    for (int st = 128; st > 0; st >>= 1) {
        if (tid < st)
            #pragma unroll
            for (int e = 0; e < Ev; e++) sm[tid][e] += sm[tid + st][e];
        __syncthreads();
    }
    if (tid == 0) {
        float lb = 0.f;
        #pragma unroll
        for (int e = 0; e < Ev; e++) { float us = sm[0][e] * (1.f / NTOK); lb += us * us; }
        out[0] = (float)Ev * lb;
    }
}

// ======================= launch =======================
static void* symaddr(const void* s) { void* p = nullptr; cudaGetSymbolAddress(&p, s); return p; }

extern "C" void kernel_launch(void* const* d_in, const int* in_sizes, int n_in,
                              void* d_out, int out_size)
{
    (void)in_sizes; (void)n_in;
    const float* x    = (const float*)d_in[0];
    const float* inw  = (const float*)d_in[1];
    const float* inb  = (const float*)d_in[2];
    const float* outw = (const float*)d_in[3];
    const float* outb = (const float*)d_in[4];
    const float* ln1g = (const float*)d_in[5];
    const float* ln1b = (const float*)d_in[6];
    const float* gw   = (const float*)d_in[7];
    const float* gb   = (const float*)d_in[8];
    const float* w1   = (const float*)d_in[9];
    const float* b1   = (const float*)d_in[10];
    const float* w2   = (const float*)d_in[11];
    const float* b2   = (const float*)d_in[12];
    const float* ln2g = (const float*)d_in[13];
    const float* ln2b = (const float*)d_in[14];
    float* out = (float*)d_out;

    __half* p_xh    = (__half*)symaddr(g_xh);
    __half* p_qkvh  = (__half*)symaddr(g_qkvh);
    __half* p_ctxh  = (__half*)symaddr(g_ctxh);
    __half* p_xgh   = (__half*)symaddr(g_xgh);
    __half* p_hh    = (__half*)symaddr(g_hh);
    __half* p_inwh  = (__half*)symaddr(g_inwh);
    __half* p_outwh = (__half*)symaddr(g_outwh);
    __half* p_w1h   = (__half*)symaddr(g_w1h);
    __half* p_w2h   = (__half*)symaddr(g_w2h);
    float* p_ao   = (float*)symaddr(g_attnout);
    float* p_x1   = (float*)symaddr(g_x1);
    float* p_eo   = (float*)symaddr(g_eo);
    int*   p_Mpad = (int*)symaddr(g_Mpad);
    int*   p_off  = (int*)symaddr(g_off);

    cudaFuncSetAttribute(gemm_h, cudaFuncAttributeMaxDynamicSharedMemorySize, GSMEMH);
    cudaFuncSetAttribute(k_attn_h, cudaFuncAttributeMaxDynamicSharedMemorySize, ASMEMH);

    // side stream + events (created once on the first, uncaptured call)
    static cudaStream_t s_side = nullptr;
    static cudaEvent_t ev_fork = nullptr, ev_join = nullptr, ev_gate = nullptr, ev_lb = nullptr;
    if (!s_side) {
        cudaStreamCreateWithFlags(&s_side, cudaStreamNonBlocking);
        cudaEventCreateWithFlags(&ev_fork, cudaEventDisableTiming);
        cudaEventCreateWithFlags(&ev_join, cudaEventDisableTiming);
        cudaEventCreateWithFlags(&ev_gate, cudaEventDisableTiming);
        cudaEventCreateWithFlags(&ev_lb, cudaEventDisableTiming);
    }

    // ---- fork: w1/w2 conversions run on side stream (needed at step 10)
    cudaEventRecord(ev_fork, 0);
    cudaStreamWaitEvent(s_side, ev_fork, 0);
    {
        long n1 = (long)Ev * FFv * Dv;
        int n4 = (int)(n1 / 4);
        k_f2h<<<(n4 + 255) / 256, 256, 0, s_side>>>((const float4*)w1, (__half2*)p_w1h, n4);
        k_f2h<<<(n4 + 255) / 256, 256, 0, s_side>>>((const float4*)w2, (__half2*)p_w2h, n4);
    }
    cudaEventRecord(ev_join, s_side);

    // ---- main stream: conversions needed early
    {
        struct { const float* src; __half* dst; long n; } cv[3] = {
            { x,    p_xh,    (long)NTOK * Dv },
            { inw,  p_inwh,  (long)3 * Dv * Dv },
            { outw, p_outwh, (long)Dv * Dv },
        };
        for (int i = 0; i < 3; i++) {
            int n4 = (int)(cv[i].n / 4);
            k_f2h<<<(n4 + 255) / 256, 256>>>((const float4*)cv[i].src, (__half2*)cv[i].dst, n4);
        }
    }

    // 1. routing state init
    k_init<<<(MAXP + 255) / 256, 256>>>();

    // 2. qkv = x @ in_proj_w^T + b  -> fp16
    gemm_h<<<dim3(3 * Dv / 128, NTOK / 256), 256, GSMEMH>>>(
        p_xh, p_inwh, inb, nullptr, p_qkvh, Dv, Dv, Dv, 3 * Dv,
        nullptr, nullptr, 0, 0, 0);

    // 3. attention -> ctx (fp16)
    k_attn_h<<<dim3(Sv / 128, Bv * Hv), 128, ASMEMH>>>(p_qkvh, p_ctxh);

    // 4. attn_out = ctx @ out_w^T + b  -> fp32
    gemm_h<<<dim3(Dv / 128, NTOK / 256), 256, GSMEMH>>>(
        p_ctxh, p_outwh, outb, p_ao, nullptr, Dv, Dv, Dv, Dv,
        nullptr, nullptr, 0, 0, 0);

    // 5+6. x1 = LN1(x + attn_out) fused with gate logits/top-2
    k_addln_gate<<<NTOK, 256>>>(x, p_ao, ln1g, ln1b, gw, gb, p_x1);

    // lb_loss depends only on logits: run on side stream, overlapped
    cudaEventRecord(ev_gate, 0);
    cudaStreamWaitEvent(s_side, ev_gate, 0);
    if (out_size > NTOK * Dv) {
        k_lb<<<1, 256, 0, s_side>>>(out + (size_t)NTOK * Dv);
    }
    cudaEventRecord(ev_lb, s_side);

    // 7-8. routing (segments 256-aligned)
    k_scan<<<1, 32>>>();
    k_assign<<<(NTOK * 2 + 255) / 256, 256>>>();

    // 9. gather tokens -> fp16
    k_gather<<<MAXP, 256>>>(p_x1, p_xgh);

    // ---- join: w1/w2 fp16 must be ready before the MoE GEMMs
    cudaStreamWaitEvent(0, ev_join, 0);

    // 10. h = relu(xg @ w1[e]^T + b1[e]) -> fp16
    gemm_h<<<dim3(FFv / 128, MAXP / 256), 256, GSMEMH>>>(
        p_xgh, p_w1h, b1, nullptr, p_hh, Dv, Dv, Dv, FFv,
        p_Mpad, p_off, (long)FFv * Dv, FFv, 1);

    // 11. eo = h @ w2[e]^T + b2[e] -> fp32
    gemm_h<<<dim3(Dv / 128, MAXP / 256), 256, GSMEMH>>>(
        p_hh, p_w2h, b2, p_eo, nullptr, FFv, FFv, FFv, Dv,
        p_Mpad, p_off, (long)Dv * FFv, Dv, 0);

    // 12. out = LN2(x1 + moe)
    k_scatter_ln2<<<NTOK, 256>>>(p_x1, ln2g, ln2b, out);

    // rejoin side stream (lb) before capture ends
    cudaStreamWaitEvent(0, ev_lb, 0);
}

// round 10
// speedup vs baseline: 1.1716x; 1.1716x over previous
#include <cuda_runtime.h>
#include <cuda_fp16.h>
#include <cstdint>

#define Bv 2
#define Sv 2048
#define Dv 1024
#define Hv 16
#define HDv 64
#define FFv 4096
#define Ev 8
#define NTOK (Bv*Sv)          // 4096
#define MAXP 9216             // 2*NTOK + 8*128 padding
#define LNEPS 1e-5f

// ---------------- scratch (device globals; no runtime alloc) ----------------
__device__ __half g_xh[(size_t)NTOK * Dv];
__device__ __half g_qkvh[(size_t)NTOK * 3 * Dv];
__device__ __half g_ctxh[(size_t)NTOK * Dv];
__device__ __half g_xgh[(size_t)MAXP * Dv];
__device__ __half g_hh[(size_t)MAXP * FFv];
__device__ __half g_inwh[(size_t)3 * Dv * Dv];
__device__ __half g_outwh[(size_t)Dv * Dv];
__device__ __half g_w1h[(size_t)Ev * FFv * Dv];
__device__ __half g_w2h[(size_t)Ev * Dv * FFv];
__device__ float g_attnout[(size_t)NTOK * Dv];
__device__ float g_x1[(size_t)NTOK * Dv];
__device__ float g_eo[(size_t)MAXP * Dv];
__device__ float g_logits[(size_t)NTOK * Ev];
__device__ float g_topw[(size_t)NTOK * 2];
__device__ int   g_topE[(size_t)NTOK * 2];
__device__ int   g_pos[(size_t)NTOK * 2];
__device__ int   g_counts[Ev];
__device__ int   g_cursor[Ev];
__device__ int   g_off[Ev + 1];
__device__ int   g_Mpad[1];
__device__ int   g_gather[MAXP];

// ======================= PTX helpers =======================
__device__ __forceinline__ unsigned smem_u32(const void* p) {
    unsigned a;
    asm("{ .reg .u64 t; cvta.to.shared.u64 t, %1; cvt.u32.u64 %0, t; }" : "=r"(a) : "l"(p));
    return a;
}
__device__ __forceinline__ void cpa16(unsigned dst, const void* src) {
    asm volatile("cp.async.cg.shared.global [%0], [%1], 16;" :: "r"(dst), "l"(src));
}
__device__ __forceinline__ void ldsm_x4(unsigned& r0, unsigned& r1, unsigned& r2, unsigned& r3, unsigned a) {
    asm volatile("ldmatrix.sync.aligned.m8n8.x4.shared.b16 {%0,%1,%2,%3}, [%4];"
        : "=r"(r0), "=r"(r1), "=r"(r2), "=r"(r3) : "r"(a));
}
__device__ __forceinline__ void ldsm_x2t(unsigned& r0, unsigned& r1, unsigned a) {
    asm volatile("ldmatrix.sync.aligned.m8n8.x2.trans.shared.b16 {%0,%1}, [%2];"
        : "=r"(r0), "=r"(r1) : "r"(a));
}
__device__ __forceinline__ void mma_f16(float* c,
    unsigned a0, unsigned a1, unsigned a2, unsigned a3, unsigned b0, unsigned b1)
{
    asm volatile(
        "mma.sync.aligned.m16n8k16.row.col.f32.f16.f16.f32 "
        "{%0,%1,%2,%3}, {%4,%5,%6,%7}, {%8,%9}, {%0,%1,%2,%3};"
        : "+f"(c[0]), "+f"(c[1]), "+f"(c[2]), "+f"(c[3])
        : "r"(a0), "r"(a1), "r"(a2), "r"(a3), "r"(b0), "r"(b1));
}
__device__ __forceinline__ unsigned pack_h2(float a, float b) {
    __half2 h = __floats2half2_rn(a, b);
    return *reinterpret_cast<unsigned*>(&h);
}

extern __shared__ float smem_f[];

// ======================= fp32 -> fp16 converter =======================
__global__ __launch_bounds__(256) void k_f2h(const float4* __restrict__ in,
                                             __half2* __restrict__ out, int n4)
{
    int i = blockIdx.x * blockDim.x + threadIdx.x;
    if (i >= n4) return;
    float4 v = in[i];
    out[2 * i]     = __floats2half2_rn(v.x, v.y);
    out[2 * i + 1] = __floats2half2_rn(v.z, v.w);
}

// ======================= fp16 mma GEMM =======================
// C[M,N] = A[M,K]h * B[N,K]h^T + bias. 128x128 CTA, K-tile 32, 5 stages,
// single __syncthreads per k-iter. 128 threads: 4 warps (2x2), 64x64 each.
#define GSTR 40                         // smem row stride in halfs (80B)
#define GTILE_H (128 * GSTR)            // 5120 halfs per matrix
#define GSTAGE_H (2 * GTILE_H)          // 10240 halfs per stage
#define NST 5
#define GSMEMH (NST * GSTAGE_H * 2)     // 102400 bytes

__device__ __forceinline__ void load_tile_h(unsigned sBase,
    const __half* __restrict__ A, int lda, const __half* __restrict__ Bm, int ldb,
    int row0, int col0, int k0, int tid)
{
    #pragma unroll
    for (int i = 0; i < 4; i++) {
        int idx = i * 128 + tid;
        int r = idx >> 2, c = idx & 3;
        unsigned doff = (unsigned)((r * GSTR + c * 8) * 2);
        cpa16(sBase + doff, A + (long)(row0 + r) * lda + k0 + c * 8);
        cpa16(sBase + GTILE_H * 2 + doff, Bm + (long)(col0 + r) * ldb + k0 + c * 8);
    }
}

__global__ __launch_bounds__(128, 2) void gemm_h(
    const __half* __restrict__ A, const __half* __restrict__ Bm,
    const float* __restrict__ bias, float* __restrict__ C, __half* __restrict__ Ch,
    int Kd, int lda, int ldb, int ldc,
    const int* __restrict__ dM, const int* __restrict__ exp_off,
    long bStride, int biasStride, int relu)
{
    int row0 = blockIdx.y * 128;
    if (dM && row0 >= *dM) return;
    int col0 = blockIdx.x * 128;
    if (exp_off) {
        int e = 0;
        while (row0 >= exp_off[e + 1]) e++;
        Bm += (long)e * bStride;
        bias += (long)e * biasStride;
    }
    int tid = threadIdx.x, lane = tid & 31, wid = tid >> 5;
    int warp_m = wid >> 1, warp_n = wid & 1;
    unsigned sb = smem_u32(smem_f);

    float acc[4][8][4];
    #pragma unroll
    for (int mt = 0; mt < 4; mt++)
        #pragma unroll
        for (int nt = 0; nt < 8; nt++)
            #pragma unroll
            for (int j = 0; j < 4; j++) acc[mt][nt][j] = 0.f;

    int nK = Kd / 32;
    #pragma unroll
    for (int s = 0; s < NST - 1; s++) {
        load_tile_h(sb + s * GSTAGE_H * 2, A, lda, Bm, ldb, row0, col0, s * 32, tid);
        asm volatile("cp.async.commit_group;" ::: "memory");
    }

    // ldmatrix per-lane addressing
    int arow = lane & 15, akb = lane >> 4;
    int bnrow = (lane & 7) + ((lane >> 4) & 1) * 8;
    int bkb = (lane >> 3) & 1;

    for (int kt = 0; kt < nK; kt++) {
        asm volatile("cp.async.wait_group 3;" ::: "memory");
        __syncthreads();
        // issue loads for stage kt+NST-1 (slot freed by the barrier)
        if (kt + NST - 1 < nK)
            load_tile_h(sb + ((kt + NST - 1) % NST) * GSTAGE_H * 2, A, lda, Bm, ldb,
                        row0, col0, (kt + NST - 1) * 32, tid);
        asm volatile("cp.async.commit_group;" ::: "memory");

        unsigned sA = sb + (kt % NST) * GSTAGE_H * 2;
        unsigned sB = sA + GTILE_H * 2;

        #pragma unroll
        for (int ks = 0; ks < 2; ks++) {
            unsigned af[4][4], bf[4][4];
            #pragma unroll
            for (int mt = 0; mt < 4; mt++) {
                unsigned addr = sA + (unsigned)(((warp_m * 64 + mt * 16 + arow) * GSTR
                                 + ks * 16 + akb * 8) * 2);
                ldsm_x4(af[mt][0], af[mt][1], af[mt][2], af[mt][3], addr);
            }
            #pragma unroll
            for (int nt2 = 0; nt2 < 4; nt2++) {
                unsigned addr = sB + (unsigned)(((warp_n * 64 + nt2 * 16 + bnrow) * GSTR
                                 + ks * 16 + bkb * 8) * 2);
                ldsm_x4(bf[nt2][0], bf[nt2][1], bf[nt2][2], bf[nt2][3], addr);
            }
            #pragma unroll
            for (int mt = 0; mt < 4; mt++)
                #pragma unroll
                for (int nt2 = 0; nt2 < 4; nt2++) {
                    mma_f16(acc[mt][2 * nt2],     af[mt][0], af[mt][1], af[mt][2], af[mt][3],
                            bf[nt2][0], bf[nt2][1]);
                    mma_f16(acc[mt][2 * nt2 + 1], af[mt][0], af[mt][1], af[mt][2], af[mt][3],
                            bf[nt2][2], bf[nt2][3]);
                }
        }
    }

    int g = lane >> 2, j = lane & 3;
    #pragma unroll
    for (int mt = 0; mt < 4; mt++) {
        int r = row0 + warp_m * 64 + mt * 16 + g;
        #pragma unroll
        for (int nt = 0; nt < 8; nt++) {
            int cg = col0 + warp_n * 64 + nt * 8 + j * 2;
            float b0 = bias[cg], b1 = bias[cg + 1];
            float v0 = acc[mt][nt][0] + b0, v1 = acc[mt][nt][1] + b1;
            float v2 = acc[mt][nt][2] + b0, v3 = acc[mt][nt][3] + b1;
            if (relu) {
                v0 = fmaxf(v0, 0.f); v1 = fmaxf(v1, 0.f);
                v2 = fmaxf(v2, 0.f); v3 = fmaxf(v3, 0.f);
            }
            if (Ch) {
                *(__half2*)(Ch + (long)r * ldc + cg) = __floats2half2_rn(v0, v1);
                *(__half2*)(Ch + (long)(r + 8) * ldc + cg) = __floats2half2_rn(v2, v3);
            } else {
                *(float2*)(C + (long)r * ldc + cg) = make_float2(v0, v1);
                *(float2*)(C + (long)(r + 8) * ldc + cg) = make_float2(v2, v3);
            }
        }
    }
}

// ======================= fp16 tensor-core flash attention =======================
// CTA: 128 queries (4 warps x 32 rows), 64-key tiles, double-buffered.
#define ASTR 72
#define AQ_OFF 0
#define AK_OFF (128 * ASTR)                 // 9216
#define AV_OFF (AK_OFF + 2 * 64 * ASTR)     // 18432
#define ASMEMH ((AV_OFF + 2 * 64 * ASTR) * 2)   // 55296 bytes

__global__ __launch_bounds__(128) void k_attn_h(const __half* __restrict__ qkv,
                                                __half* __restrict__ ctx)
{
    __half* sm = (__half*)smem_f;
    int tid = threadIdx.x, lane = tid & 31, wid = tid >> 5;
    int b = blockIdx.y >> 4, h = blockIdx.y & 15;
    int q0 = blockIdx.x * 128;
    const __half* base = qkv + (long)b * Sv * (3 * Dv) + h * HDv;
    unsigned sb = smem_u32(sm);
    int g = lane >> 2, j = lane & 3;
    int qb = wid * 32;
    int arow = lane & 15;
    int akb = lane >> 4;
    int l2 = lane & 15;

    #pragma unroll
    for (int i = 0; i < 8; i++) {
        int idx = i * 128 + tid;
        int r = idx >> 3, c = idx & 7;
        cpa16(sb + (unsigned)((AQ_OFF + r * ASTR + c * 8) * 2),
              base + (long)(q0 + r) * (3 * Dv) + c * 8);
    }
    #pragma unroll
    for (int i = 0; i < 4; i++) {
        int idx = i * 128 + tid;
        int r = idx >> 3, c = idx & 7;
        cpa16(sb + (unsigned)((AK_OFF + r * ASTR + c * 8) * 2), base + (long)r * (3 * Dv) + Dv + c * 8);
        cpa16(sb + (unsigned)((AV_OFF + r * ASTR + c * 8) * 2), base + (long)r * (3 * Dv) + 2 * Dv + c * 8);
    }
    asm volatile("cp.async.commit_group;" ::: "memory");
    asm volatile("cp.async.wait_group 0;" ::: "memory");
    __syncthreads();

    unsigned qf[2][4][4];
    #pragma unroll
    for (int mt = 0; mt < 2; mt++)
        #pragma unroll
        for (int ks = 0; ks < 4; ks++) {
            unsigned addr = sb + (unsigned)(((qb + mt * 16 + arow) * ASTR + ks * 16 + akb * 8) * 2);
            ldsm_x4(qf[mt][ks][0], qf[mt][ks][1], qf[mt][ks][2], qf[mt][ks][3], addr);
        }

    float Oa[2][8][4];
    float mrow[4], lrow[4];
    #pragma unroll
    for (int i = 0; i < 4; i++) { mrow[i] = -1e30f; lrow[i] = 0.f; }
    #pragma unroll
    for (int mt = 0; mt < 2; mt++)
        #pragma unroll
        for (int nt = 0; nt < 8; nt++)
            #pragma unroll
            for (int q = 0; q < 4; q++) Oa[mt][nt][q] = 0.f;

    for (int kt = 0; kt < Sv / 64; kt++) {
        int st = kt & 1;
        if (kt + 1 < Sv / 64) {
            int st2 = (kt + 1) & 1;
            #pragma unroll
            for (int i = 0; i < 4; i++) {
                int idx = i * 128 + tid;
                int r = idx >> 3, c = idx & 7;
                long gr = (long)((kt + 1) * 64 + r) * (3 * Dv);
                cpa16(sb + (unsigned)((AK_OFF + st2 * 64 * ASTR + r * ASTR + c * 8) * 2), base + gr + Dv + c * 8);
                cpa16(sb + (unsigned)((AV_OFF + st2 * 64 * ASTR + r * ASTR + c * 8) * 2), base + gr + 2 * Dv + c * 8);
            }
            asm volatile("cp.async.commit_group;" ::: "memory");
            asm volatile("cp.async.wait_group 1;" ::: "memory");
        } else {
            asm volatile("cp.async.wait_group 0;" ::: "memory");
        }
        __syncthreads();

        unsigned sK = sb + (unsigned)((AK_OFF + st * 64 * ASTR) * 2);
        unsigned sV = sb + (unsigned)((AV_OFF + st * 64 * ASTR) * 2);

        float sacc[2][8][4];
        #pragma unroll
        for (int mt = 0; mt < 2; mt++)
            #pragma unroll
            for (int nt = 0; nt < 8; nt++)
                #pragma unroll
                for (int q = 0; q < 4; q++) sacc[mt][nt][q] = 0.f;

        #pragma unroll
        for (int ks = 0; ks < 4; ks++) {
            unsigned bf[4][4];
            #pragma unroll
            for (int nt2 = 0; nt2 < 4; nt2++) {
                unsigned addr = sK + (unsigned)(((nt2 * 16 + (lane & 7) + ((lane >> 4) & 1) * 8) * ASTR
                                 + ks * 16 + ((lane >> 3) & 1) * 8) * 2);
                ldsm_x4(bf[nt2][0], bf[nt2][1], bf[nt2][2], bf[nt2][3], addr);
            }
            #pragma unroll
            for (int mt = 0; mt < 2; mt++)
                #pragma unroll
                for (int nt2 = 0; nt2 < 4; nt2++) {
                    mma_f16(sacc[mt][2 * nt2],     qf[mt][ks][0], qf[mt][ks][1], qf[mt][ks][2], qf[mt][ks][3],
                            bf[nt2][0], bf[nt2][1]);
                    mma_f16(sacc[mt][2 * nt2 + 1], qf[mt][ks][0], qf[mt][ks][1], qf[mt][ks][2], qf[mt][ks][3],
                            bf[nt2][2], bf[nt2][3]);
                }
        }

        #pragma unroll
        for (int mt = 0; mt < 2; mt++)
            #pragma unroll
            for (int hh = 0; hh < 2; hh++) {
                int ri = mt * 2 + hh;
                float rmax = -1e30f;
                #pragma unroll
                for (int nt = 0; nt < 8; nt++) {
                    float v0 = sacc[mt][nt][hh * 2] * 0.125f;
                    float v1 = sacc[mt][nt][hh * 2 + 1] * 0.125f;
                    sacc[mt][nt][hh * 2] = v0; sacc[mt][nt][hh * 2 + 1] = v1;
                    rmax = fmaxf(rmax, fmaxf(v0, v1));
                }
                rmax = fmaxf(rmax, __shfl_xor_sync(0xffffffffu, rmax, 1));
                rmax = fmaxf(rmax, __shfl_xor_sync(0xffffffffu, rmax, 2));
                float mnew = fmaxf(mrow[ri], rmax);
                float corr = __expf(mrow[ri] - mnew);
                mrow[ri] = mnew;
                float ps = 0.f;
                #pragma unroll
                for (int nt = 0; nt < 8; nt++) {
                    float p0 = __expf(sacc[mt][nt][hh * 2] - mnew);
                    float p1 = __expf(sacc[mt][nt][hh * 2 + 1] - mnew);
                    sacc[mt][nt][hh * 2] = p0; sacc[mt][nt][hh * 2 + 1] = p1;
                    ps += p0 + p1;
                }
                ps += __shfl_xor_sync(0xffffffffu, ps, 1);
                ps += __shfl_xor_sync(0xffffffffu, ps, 2);
                lrow[ri] = lrow[ri] * corr + ps;
                #pragma unroll
                for (int nt = 0; nt < 8; nt++) {
                    Oa[mt][nt][hh * 2] *= corr;
                    Oa[mt][nt][hh * 2 + 1] *= corr;
                }
            }

        #pragma unroll
        for (int ks = 0; ks < 4; ks++) {
            unsigned pa[2][4];
            #pragma unroll
            for (int mt = 0; mt < 2; mt++) {
                pa[mt][0] = pack_h2(sacc[mt][2 * ks][0],     sacc[mt][2 * ks][1]);
                pa[mt][1] = pack_h2(sacc[mt][2 * ks][2],     sacc[mt][2 * ks][3]);
                pa[mt][2] = pack_h2(sacc[mt][2 * ks + 1][0], sacc[mt][2 * ks + 1][1]);
                pa[mt][3] = pack_h2(sacc[mt][2 * ks + 1][2], sacc[mt][2 * ks + 1][3]);
            }
            #pragma unroll
            for (int nt = 0; nt < 8; nt++) {
                unsigned vb0, vb1;
                unsigned addr = sV + (unsigned)(((ks * 16 + (l2 & 7) + (l2 >> 3) * 8) * ASTR + nt * 8) * 2);
                ldsm_x2t(vb0, vb1, addr);
                #pragma unroll
                for (int mt = 0; mt < 2; mt++)
                    mma_f16(Oa[mt][nt], pa[mt][0], pa[mt][1], pa[mt][2], pa[mt][3], vb0, vb1);
            }
        }
        __syncthreads();
    }

    #pragma unroll
    for (int mt = 0; mt < 2; mt++)
        #pragma unroll
        for (int hh = 0; hh < 2; hh++) {
            float inv = 1.f / lrow[mt * 2 + hh];
            int qrow = q0 + qb + mt * 16 + g + hh * 8;
            __half* op = ctx + ((long)(b * Sv) + qrow) * Dv + h * HDv;
            #pragma unroll
            for (int nt = 0; nt < 8; nt++) {
                *(__half2*)(op + nt * 8 + 2 * j) =
                    __floats2half2_rn(Oa[mt][nt][hh * 2] * inv, Oa[mt][nt][hh * 2 + 1] * inv);
            }
        }
}

// ======================= small kernels =======================
__global__ void k_init() {
    int i = blockIdx.x * blockDim.x + threadIdx.x;
    if (i < MAXP) g_gather[i] = -1;
    if (i < Ev) g_counts[i] = 0;
}

// fused: x1 = LN1(x + attn_out); logits = x1 @ gw^T + gb; top-2 routing
__global__ __launch_bounds__(256) void k_addln_gate(const float* __restrict__ xa,
                                                    const float* __restrict__ xb,
                                                    const float* __restrict__ g,
                                                    const float* __restrict__ bt,
                                                    const float* __restrict__ gw,
                                                    const float* __restrict__ gb,
                                                    float* __restrict__ x1out)
{
    __shared__ float red[256];
    __shared__ float sm8[256 * Ev];
    int n = blockIdx.x, tid = threadIdx.x;
    const float* pa = xa + (long)n * Dv;
    const float* pb = xb + (long)n * Dv;
    float v[4]; float s = 0.f;
    #pragma unroll
    for (int i = 0; i < 4; i++) { int d = tid + i * 256; v[i] = pa[d] + pb[d]; s += v[i]; }
    red[tid] = s; __syncthreads();
    for (int st = 128; st > 0; st >>= 1) { if (tid < st) red[tid] += red[tid + st]; __syncthreads(); }
    float mean = red[0] * (1.f / Dv);
    __syncthreads();
    float vs = 0.f;
    #pragma unroll
    for (int i = 0; i < 4; i++) { float t = v[i] - mean; vs += t * t; }
    red[tid] = vs; __syncthreads();
    for (int st = 128; st > 0; st >>= 1) { if (tid < st) red[tid] += red[tid + st]; __syncthreads(); }
    float rstd = rsqrtf(red[0] * (1.f / Dv) + LNEPS);

    float p[Ev];
    #pragma unroll
    for (int e = 0; e < Ev; e++) p[e] = 0.f;
    #pragma unroll
    for (int i = 0; i < 4; i++) {
        int d = tid + i * 256;
        float xv = (v[i] - mean) * rstd * g[d] + bt[d];
        x1out[(long)n * Dv + d] = xv;
        #pragma unroll
        for (int e = 0; e < Ev; e++) p[e] += xv * gw[e * Dv + d];
    }
    #pragma unroll
    for (int e = 0; e < Ev; e++) sm8[tid * Ev + e] = p[e];
    __syncthreads();
    for (int st = 128; st > 0; st >>= 1) {
        if (tid < st)
            #pragma unroll
            for (int e = 0; e < Ev; e++) sm8[tid * Ev + e] += sm8[(tid + st) * Ev + e];
        __syncthreads();
    }
    if (tid == 0) {
        float l[Ev];
        #pragma unroll
        for (int e = 0; e < Ev; e++) { l[e] = sm8[e] + gb[e]; g_logits[(long)n * Ev + e] = l[e]; }
        int i0 = 0;
        #pragma unroll
        for (int e = 1; e < Ev; e++) if (l[e] > l[i0]) i0 = e;
        int i1 = -1;
        #pragma unroll
        for (int e = 0; e < Ev; e++) { if (e == i0) continue; if (i1 < 0 || l[e] > l[i1]) i1 = e; }
        float e1 = expf(l[i1] - l[i0]);
        float denom = 1.f + e1;
        g_topE[n * 2 + 0] = i0; g_topE[n * 2 + 1] = i1;
        g_topw[n * 2 + 0] = 1.f / denom; g_topw[n * 2 + 1] = e1 / denom;
        atomicAdd(&g_counts[i0], 1);
        atomicAdd(&g_counts[i1], 1);
    }
}

__global__ void k_scan() {
    if (threadIdx.x == 0) {
        int t = 0;
        for (int e = 0; e < Ev; e++) {
            g_off[e] = t; g_cursor[e] = t;
            t += (g_counts[e] + 127) & ~127;   // 128-aligned segments
        }
        g_off[Ev] = t;
        g_Mpad[0] = t;
    }
}

__global__ void k_assign() {
    int i = blockIdx.x * blockDim.x + threadIdx.x;
    if (i >= NTOK * 2) return;
    int e = g_topE[i];
    int p = atomicAdd(&g_cursor[e], 1);
    g_gather[p] = i >> 1;
    g_pos[i] = p;
}

__global__ __launch_bounds__(256) void k_gather(const float* __restrict__ x1,
                                                __half* __restrict__ xg)
{
    int p = blockIdx.x;
    int g = g_gather[p];
    __half2* dst = (__half2*)(xg + (long)p * Dv);
    int t = threadIdx.x;
    if (g >= 0) {
        float4 v = ((const float4*)(x1 + (long)g * Dv))[t];
        dst[2 * t]     = __floats2half2_rn(v.x, v.y);
        dst[2 * t + 1] = __floats2half2_rn(v.z, v.w);
    } else {
        dst[2 * t] = __floats2half2_rn(0.f, 0.f);
        dst[2 * t + 1] = __floats2half2_rn(0.f, 0.f);
    }
}

__global__ __launch_bounds__(256) void k_scatter_ln2(const float* __restrict__ x1,
                                                     const float* __restrict__ g,
                                                     const float* __restrict__ bt,
                                                     float* __restrict__ out)
{
    __shared__ float red[256];
    int n = blockIdx.x, tid = threadIdx.x;
    int p0 = g_pos[n * 2 + 0], p1 = g_pos[n * 2 + 1];
    float w0 = g_topw[n * 2 + 0], w1 = g_topw[n * 2 + 1];
    const float* px = x1 + (long)n * Dv;
    const float* pe0 = g_eo + (long)p0 * Dv;
    const float* pe1 = g_eo + (long)p1 * Dv;
    float v[4]; float s = 0.f;
    #pragma unroll
    for (int i = 0; i < 4; i++) {
        int d = tid + i * 256;
        v[i] = px[d] + w0 * pe0[d] + w1 * pe1[d];
        s += v[i];
    }
    red[tid] = s; __syncthreads();
    for (int st = 128; st > 0; st >>= 1) { if (tid < st) red[tid] += red[tid + st]; __syncthreads(); }
    float mean = red[0] * (1.f / Dv);
    __syncthreads();
    float vs = 0.f;
    #pragma unroll
    for (int i = 0; i < 4; i++) { float t = v[i] - mean; vs += t * t; }
    red[tid] = vs; __syncthreads();
    for (int st = 128; st > 0; st >>= 1) { if (tid < st) red[tid] += red[tid + st]; __syncthreads(); }
    float rstd = rsqrtf(red[0] * (1.f / Dv) + LNEPS);
    #pragma unroll
    for (int i = 0; i < 4; i++) {
        int d = tid + i * 256;
        out[(long)n * Dv + d] = (v[i] - mean) * rstd * g[d] + bt[d];
    }
}

__global__ __launch_bounds__(256) void k_lb(float* __restrict__ out) {
    __shared__ float sm[256][Ev];
    int tid = threadIdx.x;
    float u[Ev];
    #pragma unroll
    for (int e = 0; e < Ev; e++) u[e] = 0.f;
    for (int n = tid; n < NTOK; n += 256) {
        float l[Ev], mx = -1e30f, s = 0.f;
        #pragma unroll
        for (int e = 0; e < Ev; e++) { l[e] = g_logits[(long)n * Ev + e]; mx = fmaxf(mx, l[e]); }
        #pragma unroll
        for (int e = 0; e < Ev; e++) { l[e] = expf(l[e] - mx); s += l[e]; }
        float inv = 1.f / s;
        #pragma unroll
        for (int e = 0; e < Ev; e++) u[e] += l[e] * inv;
    }
    #pragma unroll
    for (int e = 0; e < Ev; e++) sm[tid][e] = u[e];
    __syncthreads();
    for (int st = 128; st > 0; st >>= 1) {
        if (tid < st)
            #pragma unroll
            for (int e = 0; e < Ev; e++) sm[tid][e] += sm[tid + st][e];
        __syncthreads();
    }
    if (tid == 0) {
        float lb = 0.f;
        #pragma unroll
        for (int e = 0; e < Ev; e++) { float us = sm[0][e] * (1.f / NTOK); lb += us * us; }
        out[0] = (float)Ev * lb;
    }
}

// ======================= launch =======================
static void* symaddr(const void* s) { void* p = nullptr; cudaGetSymbolAddress(&p, s); return p; }

extern "C" void kernel_launch(void* const* d_in, const int* in_sizes, int n_in,
                              void* d_out, int out_size)
{
    (void)in_sizes; (void)n_in;
    const float* x    = (const float*)d_in[0];
    const float* inw  = (const float*)d_in[1];
    const float* inb  = (const float*)d_in[2];
    const float* outw = (const float*)d_in[3];
    const float* outb = (const float*)d_in[4];
    const float* ln1g = (const float*)d_in[5];
    const float* ln1b = (const float*)d_in[6];
    const float* gw   = (const float*)d_in[7];
    const float* gb   = (const float*)d_in[8];
    const float* w1   = (const float*)d_in[9];
    const float* b1   = (const float*)d_in[10];
    const float* w2   = (const float*)d_in[11];
    const float* b2   = (const float*)d_in[12];
    const float* ln2g = (const float*)d_in[13];
    const float* ln2b = (const float*)d_in[14];
    float* out = (float*)d_out;

    __half* p_xh    = (__half*)symaddr(g_xh);
    __half* p_qkvh  = (__half*)symaddr(g_qkvh);
    __half* p_ctxh  = (__half*)symaddr(g_ctxh);
    __half* p_xgh   = (__half*)symaddr(g_xgh);
    __half* p_hh    = (__half*)symaddr(g_hh);
    __half* p_inwh  = (__half*)symaddr(g_inwh);
    __half* p_outwh = (__half*)symaddr(g_outwh);
    __half* p_w1h   = (__half*)symaddr(g_w1h);
    __half* p_w2h   = (__half*)symaddr(g_w2h);
    float* p_ao   = (float*)symaddr(g_attnout);
    float* p_x1   = (float*)symaddr(g_x1);
    float* p_eo   = (float*)symaddr(g_eo);
    int*   p_Mpad = (int*)symaddr(g_Mpad);
    int*   p_off  = (int*)symaddr(g_off);

    cudaFuncSetAttribute(gemm_h, cudaFuncAttributeMaxDynamicSharedMemorySize, GSMEMH);
    cudaFuncSetAttribute(k_attn_h, cudaFuncAttributeMaxDynamicSharedMemorySize, ASMEMH);

    // side stream + events (created once on the first, uncaptured call)
    static cudaStream_t s_side = nullptr;
    static cudaEvent_t ev_fork = nullptr, ev_join = nullptr, ev_gate = nullptr, ev_lb = nullptr;
    if (!s_side) {
        cudaStreamCreateWithFlags(&s_side, cudaStreamNonBlocking);
        cudaEventCreateWithFlags(&ev_fork, cudaEventDisableTiming);
        cudaEventCreateWithFlags(&ev_join, cudaEventDisableTiming);
        cudaEventCreateWithFlags(&ev_gate, cudaEventDisableTiming);
        cudaEventCreateWithFlags(&ev_lb, cudaEventDisableTiming);
    }

    // ---- fork: w1/w2 conversions run on side stream (needed at step 10)
    cudaEventRecord(ev_fork, 0);
    cudaStreamWaitEvent(s_side, ev_fork, 0);
    {
        long n1 = (long)Ev * FFv * Dv;
        int n4 = (int)(n1 / 4);
        k_f2h<<<(n4 + 255) / 256, 256, 0, s_side>>>((const float4*)w1, (__half2*)p_w1h, n4);
        k_f2h<<<(n4 + 255) / 256, 256, 0, s_side>>>((const float4*)w2, (__half2*)p_w2h, n4);
    }
    cudaEventRecord(ev_join, s_side);

    // ---- main stream: conversions needed early
    {
        struct { const float* src; __half* dst; long n; } cv[3] = {
            { x,    p_xh,    (long)NTOK * Dv },
            { inw,  p_inwh,  (long)3 * Dv * Dv },
            { outw, p_outwh, (long)Dv * Dv },
        };
        for (int i = 0; i < 3; i++) {
            int n4 = (int)(cv[i].n / 4);
            k_f2h<<<(n4 + 255) / 256, 256>>>((const float4*)cv[i].src, (__half2*)cv[i].dst, n4);
        }
    }

    // 1. routing state init
    k_init<<<(MAXP + 255) / 256, 256>>>();

    // 2. qkv = x @ in_proj_w^T + b  -> fp16
    gemm_h<<<dim3(3 * Dv / 128, NTOK / 128), 128, GSMEMH>>>(
        p_xh, p_inwh, inb, nullptr, p_qkvh, Dv, Dv, Dv, 3 * Dv,
        nullptr, nullptr, 0, 0, 0);

    // 3. attention -> ctx (fp16)
    k_attn_h<<<dim3(Sv / 128, Bv * Hv), 128, ASMEMH>>>(p_qkvh, p_ctxh);

    // 4. attn_out = ctx @ out_w^T + b  -> fp32
    gemm_h<<<dim3(Dv / 128, NTOK / 128), 128, GSMEMH>>>(
        p_ctxh, p_outwh, outb, p_ao, nullptr, Dv, Dv, Dv, Dv,
        nullptr, nullptr, 0, 0, 0);

    // 5+6. x1 = LN1(x + attn_out) fused with gate logits/top-2
    k_addln_gate<<<NTOK, 256>>>(x, p_ao, ln1g, ln1b, gw, gb, p_x1);

    // lb_loss depends only on logits: run on side stream, overlapped
    cudaEventRecord(ev_gate, 0);
    cudaStreamWaitEvent(s_side, ev_gate, 0);
    if (out_size > NTOK * Dv) {
        k_lb<<<1, 256, 0, s_side>>>(out + (size_t)NTOK * Dv);
    }
    cudaEventRecord(ev_lb, s_side);

    // 7-8. routing
    k_scan<<<1, 32>>>();
    k_assign<<<(NTOK * 2 + 255) / 256, 256>>>();

    // 9. gather tokens -> fp16
    k_gather<<<MAXP, 256>>>(p_x1, p_xgh);

    // ---- join: w1/w2 fp16 must be ready before the MoE GEMMs
    cudaStreamWaitEvent(0, ev_join, 0);

    // 10. h = relu(xg @ w1[e]^T + b1[e]) -> fp16
    gemm_h<<<dim3(FFv / 128, MAXP / 128), 128, GSMEMH>>>(
        p_xgh, p_w1h, b1, nullptr, p_hh, Dv, Dv, Dv, FFv,
        p_Mpad, p_off, (long)FFv * Dv, FFv, 1);

    // 11. eo = h @ w2[e]^T + b2[e] -> fp32
    gemm_h<<<dim3(Dv / 128, MAXP / 128), 128, GSMEMH>>>(
        p_hh, p_w2h, b2, p_eo, nullptr, FFv, FFv, FFv, Dv,
        p_Mpad, p_off, (long)Dv * FFv, Dv, 0);

    // 12. out = LN2(x1 + moe)
    k_scatter_ln2<<<NTOK, 256>>>(p_x1, ln2g, ln2b, out);

    // rejoin side stream (lb) before capture ends
    cudaStreamWaitEvent(0, ev_lb, 0);
}

// round 11
// speedup vs baseline: 1.2701x; 1.0841x over previous
#include <cuda_runtime.h>
#include <cuda_fp16.h>
#include <cstdint>

#define Bv 2
#define Sv 2048
#define Dv 1024
#define Hv 16
#define HDv 64
#define FFv 4096
#define Ev 8
#define NTOK (Bv*Sv)          // 4096
#define MAXP 9216             // 2*NTOK + 8*128 padding
#define LNEPS 1e-5f

// ---------------- scratch (device globals; no runtime alloc) ----------------
__device__ __half g_xh[(size_t)NTOK * Dv];
__device__ __half g_qkvh[(size_t)NTOK * 3 * Dv];
__device__ __half g_ctxh[(size_t)NTOK * Dv];
__device__ __half g_x1h[(size_t)NTOK * Dv];
__device__ __half g_hh[(size_t)MAXP * FFv];
__device__ __half g_inwh[(size_t)3 * Dv * Dv];
__device__ __half g_outwh[(size_t)Dv * Dv];
__device__ __half g_w1h[(size_t)Ev * FFv * Dv];
__device__ __half g_w2h[(size_t)Ev * Dv * FFv];
__device__ float g_attnout[(size_t)NTOK * Dv];
__device__ float g_x1[(size_t)NTOK * Dv];
__device__ float g_eo[(size_t)MAXP * Dv];
__device__ float g_logits[(size_t)NTOK * Ev];
__device__ float g_topw[(size_t)NTOK * 2];
__device__ int   g_topE[(size_t)NTOK * 2];
__device__ int   g_pos[(size_t)NTOK * 2];
__device__ int   g_counts[Ev];
__device__ int   g_cursor[Ev];
__device__ int   g_off[Ev + 1];
__device__ int   g_Mpad[1];
__device__ int   g_gather[MAXP];

// ======================= PTX helpers =======================
__device__ __forceinline__ unsigned smem_u32(const void* p) {
    unsigned a;
    asm("{ .reg .u64 t; cvta.to.shared.u64 t, %1; cvt.u32.u64 %0, t; }" : "=r"(a) : "l"(p));
    return a;
}
__device__ __forceinline__ void cpa16(unsigned dst, const void* src) {
    asm volatile("cp.async.cg.shared.global [%0], [%1], 16;" :: "r"(dst), "l"(src));
}
__device__ __forceinline__ void cpa16z(unsigned dst, const void* src, int sz) {
    asm volatile("cp.async.cg.shared.global [%0], [%1], 16, %2;" :: "r"(dst), "l"(src), "r"(sz));
}
__device__ __forceinline__ void ldsm_x4(unsigned& r0, unsigned& r1, unsigned& r2, unsigned& r3, unsigned a) {
    asm volatile("ldmatrix.sync.aligned.m8n8.x4.shared.b16 {%0,%1,%2,%3}, [%4];"
        : "=r"(r0), "=r"(r1), "=r"(r2), "=r"(r3) : "r"(a));
}
__device__ __forceinline__ void ldsm_x2t(unsigned& r0, unsigned& r1, unsigned a) {
    asm volatile("ldmatrix.sync.aligned.m8n8.x2.trans.shared.b16 {%0,%1}, [%2];"
        : "=r"(r0), "=r"(r1) : "r"(a));
}
__device__ __forceinline__ void mma_f16(float* c,
    unsigned a0, unsigned a1, unsigned a2, unsigned a3, unsigned b0, unsigned b1)
{
    asm volatile(
        "mma.sync.aligned.m16n8k16.row.col.f32.f16.f16.f32 "
        "{%0,%1,%2,%3}, {%4,%5,%6,%7}, {%8,%9}, {%0,%1,%2,%3};"
        : "+f"(c[0]), "+f"(c[1]), "+f"(c[2]), "+f"(c[3])
        : "r"(a0), "r"(a1), "r"(a2), "r"(a3), "r"(b0), "r"(b1));
}
__device__ __forceinline__ unsigned pack_h2(float a, float b) {
    __half2 h = __floats2half2_rn(a, b);
    return *reinterpret_cast<unsigned*>(&h);
}

extern __shared__ float smem_f[];

// ======================= fp32 -> fp16 converter =======================
__global__ __launch_bounds__(256) void k_f2h(const float4* __restrict__ in,
                                             __half2* __restrict__ out, int n4)
{
    int i = blockIdx.x * blockDim.x + threadIdx.x;
    if (i >= n4) return;
    float4 v = in[i];
    out[2 * i]     = __floats2half2_rn(v.x, v.y);
    out[2 * i + 1] = __floats2half2_rn(v.z, v.w);
}

// ======================= fused prep: x/inw/outw conversion + routing init ====
#define PREP_NX 4096   // NTOK*Dv/4/256
#define PREP_NI 3072   // 3*Dv*Dv/4/256
#define PREP_NO 1024   // Dv*Dv/4/256
#define PREP_GRID (PREP_NX + PREP_NI + PREP_NO + 36)
__global__ __launch_bounds__(256) void k_prep(
    const float4* __restrict__ x, const float4* __restrict__ inw,
    const float4* __restrict__ outw,
    __half2* __restrict__ xh, __half2* __restrict__ inwh, __half2* __restrict__ outwh)
{
    int b = blockIdx.x, tid = threadIdx.x;
    if (b < PREP_NX) {
        int i = b * 256 + tid;
        float4 v = x[i];
        xh[2 * i]     = __floats2half2_rn(v.x, v.y);
        xh[2 * i + 1] = __floats2half2_rn(v.z, v.w);
    } else if (b < PREP_NX + PREP_NI) {
        int i = (b - PREP_NX) * 256 + tid;
        float4 v = inw[i];
        inwh[2 * i]     = __floats2half2_rn(v.x, v.y);
        inwh[2 * i + 1] = __floats2half2_rn(v.z, v.w);
    } else if (b < PREP_NX + PREP_NI + PREP_NO) {
        int i = (b - PREP_NX - PREP_NI) * 256 + tid;
        float4 v = outw[i];
        outwh[2 * i]     = __floats2half2_rn(v.x, v.y);
        outwh[2 * i + 1] = __floats2half2_rn(v.z, v.w);
    } else {
        int i = (b - PREP_NX - PREP_NI - PREP_NO) * 256 + tid;
        if (i < MAXP) g_gather[i] = -1;
        if (i < Ev) g_counts[i] = 0;
    }
}

// ======================= fp16 mma GEMM =======================
// C[M,N] = A[M,K]h * B[N,K]h^T + bias (+ optional fp32 residual R, optional
// A row gather). 128x128 CTA, K-tile 32, 4 stages, single sync per k-iter.
// 128 threads: 4 warps (2x2), 64x64 each.
#define GSTR 40                         // smem row stride in halfs (80B)
#define GTILE_H (128 * GSTR)            // 5120 halfs per matrix
#define GSTAGE_H (2 * GTILE_H)          // 10240 halfs per stage
#define NST 4
#define GSMEMH (NST * GSTAGE_H * 2)     // 81920 bytes

__device__ __forceinline__ void load_tileA(unsigned sBase,
    const __half* __restrict__ A, int lda, const int* rg, int k0, int tid)
{
    int c = tid & 3;
    #pragma unroll
    for (int i = 0; i < 4; i++) {
        int r = i * 32 + (tid >> 2);
        unsigned doff = (unsigned)((r * GSTR + c * 8) * 2);
        int g = rg[i];
        const __half* src = (g >= 0) ? (A + (long)g * lda + k0 + c * 8) : A;
        cpa16z(sBase + doff, src, (g >= 0) ? 16 : 0);
    }
}
__device__ __forceinline__ void load_tileB(unsigned sBase,
    const __half* __restrict__ Bm, int ldb, int col0, int k0, int tid)
{
    int c = tid & 3;
    #pragma unroll
    for (int i = 0; i < 4; i++) {
        int r = i * 32 + (tid >> 2);
        unsigned doff = (unsigned)((r * GSTR + c * 8) * 2);
        cpa16(sBase + GTILE_H * 2 + doff, Bm + (long)(col0 + r) * ldb + k0 + c * 8);
    }
}

__global__ __launch_bounds__(128, 2) void gemm_h(
    const __half* __restrict__ A, const __half* __restrict__ Bm,
    const float* __restrict__ bias, float* __restrict__ C, __half* __restrict__ Ch,
    const float* __restrict__ Rres,
    int Kd, int lda, int ldb, int ldc,
    const int* __restrict__ dM, const int* __restrict__ exp_off,
    const int* __restrict__ row_map,
    long bStride, int biasStride, int relu)
{
    int row0 = blockIdx.y * 128;
    if (dM && row0 >= *dM) return;
    int col0 = blockIdx.x * 128;
    if (exp_off) {
        int e = 0;
        while (row0 >= exp_off[e + 1]) e++;
        Bm += (long)e * bStride;
        bias += (long)e * biasStride;
    }
    int tid = threadIdx.x, lane = tid & 31, wid = tid >> 5;
    int warp_m = wid >> 1, warp_n = wid & 1;
    unsigned sb = smem_u32(smem_f);

    // per-thread A-row gather indices (loop-invariant)
    int rg[4];
    #pragma unroll
    for (int i = 0; i < 4; i++) {
        int r = row0 + i * 32 + (tid >> 2);
        rg[i] = row_map ? row_map[r] : r;
    }

    float acc[4][8][4];
    #pragma unroll
    for (int mt = 0; mt < 4; mt++)
        #pragma unroll
        for (int nt = 0; nt < 8; nt++)
            #pragma unroll
            for (int j = 0; j < 4; j++) acc[mt][nt][j] = 0.f;

    int nK = Kd / 32;
    #pragma unroll
    for (int s = 0; s < NST - 1; s++) {
        load_tileA(sb + s * GSTAGE_H * 2, A, lda, rg, s * 32, tid);
        load_tileB(sb + s * GSTAGE_H * 2, Bm, ldb, col0, s * 32, tid);
        asm volatile("cp.async.commit_group;" ::: "memory");
    }

    int arow = lane & 15, akb = lane >> 4;
    int bnrow = (lane & 7) + ((lane >> 4) & 1) * 8;
    int bkb = (lane >> 3) & 1;

    for (int kt = 0; kt < nK; kt++) {
        asm volatile("cp.async.wait_group 2;" ::: "memory");
        __syncthreads();
        if (kt + NST - 1 < nK) {
            unsigned s0 = sb + ((kt + NST - 1) % NST) * GSTAGE_H * 2;
            load_tileA(s0, A, lda, rg, (kt + NST - 1) * 32, tid);
            load_tileB(s0, Bm, ldb, col0, (kt + NST - 1) * 32, tid);
        }
        asm volatile("cp.async.commit_group;" ::: "memory");

        unsigned sA = sb + (kt % NST) * GSTAGE_H * 2;
        unsigned sB = sA + GTILE_H * 2;

        #pragma unroll
        for (int ks = 0; ks < 2; ks++) {
            unsigned af[4][4], bf[4][4];
            #pragma unroll
            for (int mt = 0; mt < 4; mt++) {
                unsigned addr = sA + (unsigned)(((warp_m * 64 + mt * 16 + arow) * GSTR
                                 + ks * 16 + akb * 8) * 2);
                ldsm_x4(af[mt][0], af[mt][1], af[mt][2], af[mt][3], addr);
            }
            #pragma unroll
            for (int nt2 = 0; nt2 < 4; nt2++) {
                unsigned addr = sB + (unsigned)(((warp_n * 64 + nt2 * 16 + bnrow) * GSTR
                                 + ks * 16 + bkb * 8) * 2);
                ldsm_x4(bf[nt2][0], bf[nt2][1], bf[nt2][2], bf[nt2][3], addr);
            }
            #pragma unroll
            for (int mt = 0; mt < 4; mt++)
                #pragma unroll
                for (int nt2 = 0; nt2 < 4; nt2++) {
                    mma_f16(acc[mt][2 * nt2],     af[mt][0], af[mt][1], af[mt][2], af[mt][3],
                            bf[nt2][0], bf[nt2][1]);
                    mma_f16(acc[mt][2 * nt2 + 1], af[mt][0], af[mt][1], af[mt][2], af[mt][3],
                            bf[nt2][2], bf[nt2][3]);
                }
        }
    }

    int g = lane >> 2, j = lane & 3;
    #pragma unroll
    for (int mt = 0; mt < 4; mt++) {
        int r = row0 + warp_m * 64 + mt * 16 + g;
        #pragma unroll
        for (int nt = 0; nt < 8; nt++) {
            int cg = col0 + warp_n * 64 + nt * 8 + j * 2;
            float b0 = bias[cg], b1 = bias[cg + 1];
            float v0 = acc[mt][nt][0] + b0, v1 = acc[mt][nt][1] + b1;
            float v2 = acc[mt][nt][2] + b0, v3 = acc[mt][nt][3] + b1;
            if (Rres) {
                float2 r0 = *(const float2*)(Rres + (long)r * ldc + cg);
                float2 r1 = *(const float2*)(Rres + (long)(r + 8) * ldc + cg);
                v0 += r0.x; v1 += r0.y; v2 += r1.x; v3 += r1.y;
            }
            if (relu) {
                v0 = fmaxf(v0, 0.f); v1 = fmaxf(v1, 0.f);
                v2 = fmaxf(v2, 0.f); v3 = fmaxf(v3, 0.f);
            }
            if (Ch) {
                *(__half2*)(Ch + (long)r * ldc + cg) = __floats2half2_rn(v0, v1);
                *(__half2*)(Ch + (long)(r + 8) * ldc + cg) = __floats2half2_rn(v2, v3);
            } else {
                *(float2*)(C + (long)r * ldc + cg) = make_float2(v0, v1);
                *(float2*)(C + (long)(r + 8) * ldc + cg) = make_float2(v2, v3);
            }
        }
    }
}

// ======================= fp16 tensor-core flash attention =======================
#define ASTR 72
#define AQ_OFF 0
#define AK_OFF (128 * ASTR)
#define AV_OFF (AK_OFF + 2 * 64 * ASTR)
#define ASMEMH ((AV_OFF + 2 * 64 * ASTR) * 2)   // 55296 bytes

__global__ __launch_bounds__(128) void k_attn_h(const __half* __restrict__ qkv,
                                                __half* __restrict__ ctx)
{
    __half* sm = (__half*)smem_f;
    int tid = threadIdx.x, lane = tid & 31, wid = tid >> 5;
    int b = blockIdx.y >> 4, h = blockIdx.y & 15;
    int q0 = blockIdx.x * 128;
    const __half* base = qkv + (long)b * Sv * (3 * Dv) + h * HDv;
    unsigned sb = smem_u32(sm);
    int g = lane >> 2, j = lane & 3;
    int qb = wid * 32;
    int arow = lane & 15;
    int akb = lane >> 4;
    int l2 = lane & 15;

    #pragma unroll
    for (int i = 0; i < 8; i++) {
        int idx = i * 128 + tid;
        int r = idx >> 3, c = idx & 7;
        cpa16(sb + (unsigned)((AQ_OFF + r * ASTR + c * 8) * 2),
              base + (long)(q0 + r) * (3 * Dv) + c * 8);
    }
    #pragma unroll
    for (int i = 0; i < 4; i++) {
        int idx = i * 128 + tid;
        int r = idx >> 3, c = idx & 7;
        cpa16(sb + (unsigned)((AK_OFF + r * ASTR + c * 8) * 2), base + (long)r * (3 * Dv) + Dv + c * 8);
        cpa16(sb + (unsigned)((AV_OFF + r * ASTR + c * 8) * 2), base + (long)r * (3 * Dv) + 2 * Dv + c * 8);
    }
    asm volatile("cp.async.commit_group;" ::: "memory");
    asm volatile("cp.async.wait_group 0;" ::: "memory");
    __syncthreads();

    unsigned qf[2][4][4];
    #pragma unroll
    for (int mt = 0; mt < 2; mt++)
        #pragma unroll
        for (int ks = 0; ks < 4; ks++) {
            unsigned addr = sb + (unsigned)(((qb + mt * 16 + arow) * ASTR + ks * 16 + akb * 8) * 2);
            ldsm_x4(qf[mt][ks][0], qf[mt][ks][1], qf[mt][ks][2], qf[mt][ks][3], addr);
        }

    float Oa[2][8][4];
    float mrow[4], lrow[4];
    #pragma unroll
    for (int i = 0; i < 4; i++) { mrow[i] = -1e30f; lrow[i] = 0.f; }
    #pragma unroll
    for (int mt = 0; mt < 2; mt++)
        #pragma unroll
        for (int nt = 0; nt < 8; nt++)
            #pragma unroll
            for (int q = 0; q < 4; q++) Oa[mt][nt][q] = 0.f;

    for (int kt = 0; kt < Sv / 64; kt++) {
        int st = kt & 1;
        if (kt + 1 < Sv / 64) {
            int st2 = (kt + 1) & 1;
            #pragma unroll
            for (int i = 0; i < 4; i++) {
                int idx = i * 128 + tid;
                int r = idx >> 3, c = idx & 7;
                long gr = (long)((kt + 1) * 64 + r) * (3 * Dv);
                cpa16(sb + (unsigned)((AK_OFF + st2 * 64 * ASTR + r * ASTR + c * 8) * 2), base + gr + Dv + c * 8);
                cpa16(sb + (unsigned)((AV_OFF + st2 * 64 * ASTR + r * ASTR + c * 8) * 2), base + gr + 2 * Dv + c * 8);
            }
            asm volatile("cp.async.commit_group;" ::: "memory");
            asm volatile("cp.async.wait_group 1;" ::: "memory");
        } else {
            asm volatile("cp.async.wait_group 0;" ::: "memory");
        }
        __syncthreads();

        unsigned sK = sb + (unsigned)((AK_OFF + st * 64 * ASTR) * 2);
        unsigned sV = sb + (unsigned)((AV_OFF + st * 64 * ASTR) * 2);

        float sacc[2][8][4];
        #pragma unroll
        for (int mt = 0; mt < 2; mt++)
            #pragma unroll
            for (int nt = 0; nt < 8; nt++)
                #pragma unroll
                for (int q = 0; q < 4; q++) sacc[mt][nt][q] = 0.f;

        #pragma unroll
        for (int ks = 0; ks < 4; ks++) {
            unsigned bf[4][4];
            #pragma unroll
            for (int nt2 = 0; nt2 < 4; nt2++) {
                unsigned addr = sK + (unsigned)(((nt2 * 16 + (lane & 7) + ((lane >> 4) & 1) * 8) * ASTR
                                 + ks * 16 + ((lane >> 3) & 1) * 8) * 2);
                ldsm_x4(bf[nt2][0], bf[nt2][1], bf[nt2][2], bf[nt2][3], addr);
            }
            #pragma unroll
            for (int mt = 0; mt < 2; mt++)
                #pragma unroll
                for (int nt2 = 0; nt2 < 4; nt2++) {
                    mma_f16(sacc[mt][2 * nt2],     qf[mt][ks][0], qf[mt][ks][1], qf[mt][ks][2], qf[mt][ks][3],
                            bf[nt2][0], bf[nt2][1]);
                    mma_f16(sacc[mt][2 * nt2 + 1], qf[mt][ks][0], qf[mt][ks][1], qf[mt][ks][2], qf[mt][ks][3],
                            bf[nt2][2], bf[nt2][3]);
                }
        }

        #pragma unroll
        for (int mt = 0; mt < 2; mt++)
            #pragma unroll
            for (int hh = 0; hh < 2; hh++) {
                int ri = mt * 2 + hh;
                float rmax = -1e30f;
                #pragma unroll
                for (int nt = 0; nt < 8; nt++) {
                    float v0 = sacc[mt][nt][hh * 2] * 0.125f;
                    float v1 = sacc[mt][nt][hh * 2 + 1] * 0.125f;
                    sacc[mt][nt][hh * 2] = v0; sacc[mt][nt][hh * 2 + 1] = v1;
                    rmax = fmaxf(rmax, fmaxf(v0, v1));
                }
                rmax = fmaxf(rmax, __shfl_xor_sync(0xffffffffu, rmax, 1));
                rmax = fmaxf(rmax, __shfl_xor_sync(0xffffffffu, rmax, 2));
                float mnew = fmaxf(mrow[ri], rmax);
                float corr = __expf(mrow[ri] - mnew);
                mrow[ri] = mnew;
                float ps = 0.f;
                #pragma unroll
                for (int nt = 0; nt < 8; nt++) {
                    float p0 = __expf(sacc[mt][nt][hh * 2] - mnew);
                    float p1 = __expf(sacc[mt][nt][hh * 2 + 1] - mnew);
                    sacc[mt][nt][hh * 2] = p0; sacc[mt][nt][hh * 2 + 1] = p1;
                    ps += p0 + p1;
                }
                ps += __shfl_xor_sync(0xffffffffu, ps, 1);
                ps += __shfl_xor_sync(0xffffffffu, ps, 2);
                lrow[ri] = lrow[ri] * corr + ps;
                #pragma unroll
                for (int nt = 0; nt < 8; nt++) {
                    Oa[mt][nt][hh * 2] *= corr;
                    Oa[mt][nt][hh * 2 + 1] *= corr;
                }
            }

        #pragma unroll
        for (int ks = 0; ks < 4; ks++) {
            unsigned pa[2][4];
            #pragma unroll
            for (int mt = 0; mt < 2; mt++) {
                pa[mt][0] = pack_h2(sacc[mt][2 * ks][0],     sacc[mt][2 * ks][1]);
                pa[mt][1] = pack_h2(sacc[mt][2 * ks][2],     sacc[mt][2 * ks][3]);
                pa[mt][2] = pack_h2(sacc[mt][2 * ks + 1][0], sacc[mt][2 * ks + 1][1]);
                pa[mt][3] = pack_h2(sacc[mt][2 * ks + 1][2], sacc[mt][2 * ks + 1][3]);
            }
            #pragma unroll
            for (int nt = 0; nt < 8; nt++) {
                unsigned vb0, vb1;
                unsigned addr = sV + (unsigned)(((ks * 16 + (l2 & 7) + (l2 >> 3) * 8) * ASTR + nt * 8) * 2);
                ldsm_x2t(vb0, vb1, addr);
                #pragma unroll
                for (int mt = 0; mt < 2; mt++)
                    mma_f16(Oa[mt][nt], pa[mt][0], pa[mt][1], pa[mt][2], pa[mt][3], vb0, vb1);
            }
        }
        __syncthreads();
    }

    #pragma unroll
    for (int mt = 0; mt < 2; mt++)
        #pragma unroll
        for (int hh = 0; hh < 2; hh++) {
            float inv = 1.f / lrow[mt * 2 + hh];
            int qrow = q0 + qb + mt * 16 + g + hh * 8;
            __half* op = ctx + ((long)(b * Sv) + qrow) * Dv + h * HDv;
            #pragma unroll
            for (int nt = 0; nt < 8; nt++) {
                *(__half2*)(op + nt * 8 + 2 * j) =
                    __floats2half2_rn(Oa[mt][nt][hh * 2] * inv, Oa[mt][nt][hh * 2 + 1] * inv);
            }
        }
}

// ======================= small kernels =======================
// fused: x1 = LN1(xs); logits = x1 @ gw^T + gb; top-2 routing.
// xs already contains x + attn_out (residual fused into out-proj epilogue).
__global__ __launch_bounds__(256) void k_addln_gate(const float* __restrict__ xs,
                                                    const float* __restrict__ g,
                                                    const float* __restrict__ bt,
                                                    const float* __restrict__ gw,
                                                    const float* __restrict__ gb,
                                                    float* __restrict__ x1out,
                                                    __half* __restrict__ x1h)
{
    __shared__ float red[256];
    __shared__ float sm8[256 * Ev];
    int n = blockIdx.x, tid = threadIdx.x;
    const float* pa = xs + (long)n * Dv;
    float v[4]; float s = 0.f;
    #pragma unroll
    for (int i = 0; i < 4; i++) { int d = tid + i * 256; v[i] = pa[d]; s += v[i]; }
    red[tid] = s; __syncthreads();
    for (int st = 128; st > 0; st >>= 1) { if (tid < st) red[tid] += red[tid + st]; __syncthreads(); }
    float mean = red[0] * (1.f / Dv);
    __syncthreads();
    float vs = 0.f;
    #pragma unroll
    for (int i = 0; i < 4; i++) { float t = v[i] - mean; vs += t * t; }
    red[tid] = vs; __syncthreads();
    for (int st = 128; st > 0; st >>= 1) { if (tid < st) red[tid] += red[tid + st]; __syncthreads(); }
    float rstd = rsqrtf(red[0] * (1.f / Dv) + LNEPS);

    float p[Ev];
    #pragma unroll
    for (int e = 0; e < Ev; e++) p[e] = 0.f;
    #pragma unroll
    for (int i = 0; i < 4; i++) {
        int d = tid + i * 256;
        float xv = (v[i] - mean) * rstd * g[d] + bt[d];
        x1out[(long)n * Dv + d] = xv;
        x1h[(long)n * Dv + d] = __float2half_rn(xv);
        #pragma unroll
        for (int e = 0; e < Ev; e++) p[e] += xv * gw[e * Dv + d];
    }
    #pragma unroll
    for (int e = 0; e < Ev; e++) sm8[tid * Ev + e] = p[e];
    __syncthreads();
    for (int st = 128; st > 0; st >>= 1) {
        if (tid < st)
            #pragma unroll
            for (int e = 0; e < Ev; e++) sm8[tid * Ev + e] += sm8[(tid + st) * Ev + e];
        __syncthreads();
    }
    if (tid == 0) {
        float l[Ev];
        #pragma unroll
        for (int e = 0; e < Ev; e++) { l[e] = sm8[e] + gb[e]; g_logits[(long)n * Ev + e] = l[e]; }
        int i0 = 0;
        #pragma unroll
        for (int e = 1; e < Ev; e++) if (l[e] > l[i0]) i0 = e;
        int i1 = -1;
        #pragma unroll
        for (int e = 0; e < Ev; e++) { if (e == i0) continue; if (i1 < 0 || l[e] > l[i1]) i1 = e; }
        float e1 = expf(l[i1] - l[i0]);
        float denom = 1.f + e1;
        g_topE[n * 2 + 0] = i0; g_topE[n * 2 + 1] = i1;
        g_topw[n * 2 + 0] = 1.f / denom; g_topw[n * 2 + 1] = e1 / denom;
        atomicAdd(&g_counts[i0], 1);
        atomicAdd(&g_counts[i1], 1);
    }
}

__global__ void k_scan() {
    if (threadIdx.x == 0) {
        int t = 0;
        for (int e = 0; e < Ev; e++) {
            g_off[e] = t; g_cursor[e] = t;
            t += (g_counts[e] + 127) & ~127;
        }
        g_off[Ev] = t;
        g_Mpad[0] = t;
    }
}

__global__ void k_assign() {
    int i = blockIdx.x * blockDim.x + threadIdx.x;
    if (i >= NTOK * 2) return;
    int e = g_topE[i];
    int p = atomicAdd(&g_cursor[e], 1);
    g_gather[p] = i >> 1;
    g_pos[i] = p;
}

__global__ __launch_bounds__(256) void k_scatter_ln2(const float* __restrict__ x1,
                                                     const float* __restrict__ g,
                                                     const float* __restrict__ bt,
                                                     float* __restrict__ out)
{
    __shared__ float red[256];
    int n = blockIdx.x, tid = threadIdx.x;
    int p0 = g_pos[n * 2 + 0], p1 = g_pos[n * 2 + 1];
    float w0 = g_topw[n * 2 + 0], w1 = g_topw[n * 2 + 1];
    const float* px = x1 + (long)n * Dv;
    const float* pe0 = g_eo + (long)p0 * Dv;
    const float* pe1 = g_eo + (long)p1 * Dv;
    float v[4]; float s = 0.f;
    #pragma unroll
    for (int i = 0; i < 4; i++) {
        int d = tid + i * 256;
        v[i] = px[d] + w0 * pe0[d] + w1 * pe1[d];
        s += v[i];
    }
    red[tid] = s; __syncthreads();
    for (int st = 128; st > 0; st >>= 1) { if (tid < st) red[tid] += red[tid + st]; __syncthreads(); }
    float mean = red[0] * (1.f / Dv);
    __syncthreads();
    float vs = 0.f;
    #pragma unroll
    for (int i = 0; i < 4; i++) { float t = v[i] - mean; vs += t * t; }
    red[tid] = vs; __syncthreads();
    for (int st = 128; st > 0; st >>= 1) { if (tid < st) red[tid] += red[tid + st]; __syncthreads(); }
    float rstd = rsqrtf(red[0] * (1.f / Dv) + LNEPS);
    #pragma unroll
    for (int i = 0; i < 4; i++) {
        int d = tid + i * 256;
        out[(long)n * Dv + d] = (v[i] - mean) * rstd * g[d] + bt[d];
    }
}

__global__ __launch_bounds__(256) void k_lb(float* __restrict__ out) {
    __shared__ float sm[256][Ev];
    int tid = threadIdx.x;
    float u[Ev];
    #pragma unroll
    for (int e = 0; e < Ev; e++) u[e] = 0.f;
    for (int n = tid; n < NTOK; n += 256) {
        float l[Ev], mx = -1e30f, s = 0.f;
        #pragma unroll
        for (int e = 0; e < Ev; e++) { l[e] = g_logits[(long)n * Ev + e]; mx = fmaxf(mx, l[e]); }
        #pragma unroll
        for (int e = 0; e < Ev; e++) { l[e] = expf(l[e] - mx); s += l[e]; }
        float inv = 1.f / s;
        #pragma unroll
        for (int e = 0; e < Ev; e++) u[e] += l[e] * inv;
    }
    #pragma unroll
    for (int e = 0; e < Ev; e++) sm[tid][e] = u[e];
    __syncthreads();
    for (int st = 128; st > 0; st >>= 1) {
        if (tid < st)
            #pragma unroll
            for (int e = 0; e < Ev; e++) sm[tid][e] += sm[tid + st][e];
        __syncthreads();
    }
    if (tid == 0) {
        float lb = 0.f;
        #pragma unroll
        for (int e = 0; e < Ev; e++) { float us = sm[0][e] * (1.f / NTOK); lb += us * us; }
        out[0] = (float)Ev * lb;
    }
}

// ======================= launch =======================
static void* symaddr(const void* s) { void* p = nullptr; cudaGetSymbolAddress(&p, s); return p; }

extern "C" void kernel_launch(void* const* d_in, const int* in_sizes, int n_in,
                              void* d_out, int out_size)
{
    (void)in_sizes; (void)n_in;
    const float* x    = (const float*)d_in[0];
    const float* inw  = (const float*)d_in[1];
    const float* inb  = (const float*)d_in[2];
    const float* outw = (const float*)d_in[3];
    const float* outb = (const float*)d_in[4];
    const float* ln1g = (const float*)d_in[5];
    const float* ln1b = (const float*)d_in[6];
    const float* gw   = (const float*)d_in[7];
    const float* gb   = (const float*)d_in[8];
    const float* w1   = (const float*)d_in[9];
    const float* b1   = (const float*)d_in[10];
    const float* w2   = (const float*)d_in[11];
    const float* b2   = (const float*)d_in[12];
    const float* ln2g = (const float*)d_in[13];
    const float* ln2b = (const float*)d_in[14];
    float* out = (float*)d_out;

    __half* p_xh    = (__half*)symaddr(g_xh);
    __half* p_qkvh  = (__half*)symaddr(g_qkvh);
    __half* p_ctxh  = (__half*)symaddr(g_ctxh);
    __half* p_x1h   = (__half*)symaddr(g_x1h);
    __half* p_hh    = (__half*)symaddr(g_hh);
    __half* p_inwh  = (__half*)symaddr(g_inwh);
    __half* p_outwh = (__half*)symaddr(g_outwh);
    __half* p_w1h   = (__half*)symaddr(g_w1h);
    __half* p_w2h   = (__half*)symaddr(g_w2h);
    float* p_ao   = (float*)symaddr(g_attnout);
    float* p_x1   = (float*)symaddr(g_x1);
    float* p_eo   = (float*)symaddr(g_eo);
    int*   p_Mpad = (int*)symaddr(g_Mpad);
    int*   p_off  = (int*)symaddr(g_off);
    int*   p_gath = (int*)symaddr(g_gather);

    cudaFuncSetAttribute(gemm_h, cudaFuncAttributeMaxDynamicSharedMemorySize, GSMEMH);
    cudaFuncSetAttribute(k_attn_h, cudaFuncAttributeMaxDynamicSharedMemorySize, ASMEMH);

    // side stream + events (created once on the first, uncaptured call)
    static cudaStream_t s_side = nullptr;
    static cudaEvent_t ev_fork = nullptr, ev_join = nullptr, ev_gate = nullptr, ev_lb = nullptr;
    if (!s_side) {
        cudaStreamCreateWithFlags(&s_side, cudaStreamNonBlocking);
        cudaEventCreateWithFlags(&ev_fork, cudaEventDisableTiming);
        cudaEventCreateWithFlags(&ev_join, cudaEventDisableTiming);
        cudaEventCreateWithFlags(&ev_gate, cudaEventDisableTiming);
        cudaEventCreateWithFlags(&ev_lb, cudaEventDisableTiming);
    }

    // ---- fork: w1/w2 conversions run on side stream (needed at step 10)
    cudaEventRecord(ev_fork, 0);
    cudaStreamWaitEvent(s_side, ev_fork, 0);
    {
        long n1 = (long)Ev * FFv * Dv;
        int n4 = (int)(n1 / 4);
        k_f2h<<<(n4 + 255) / 256, 256, 0, s_side>>>((const float4*)w1, (__half2*)p_w1h, n4);
        k_f2h<<<(n4 + 255) / 256, 256, 0, s_side>>>((const float4*)w2, (__half2*)p_w2h, n4);
    }
    cudaEventRecord(ev_join, s_side);

    // ---- main stream: fused conversions (x, inw, outw) + routing init
    k_prep<<<PREP_GRID, 256>>>((const float4*)x, (const float4*)inw, (const float4*)outw,
                               (__half2*)p_xh, (__half2*)p_inwh, (__half2*)p_outwh);

    // 2. qkv = x @ in_proj_w^T + b  -> fp16
    gemm_h<<<dim3(3 * Dv / 128, NTOK / 128), 128, GSMEMH>>>(
        p_xh, p_inwh, inb, nullptr, p_qkvh, nullptr, Dv, Dv, Dv, 3 * Dv,
        nullptr, nullptr, nullptr, 0, 0, 0);

    // 3. attention -> ctx (fp16)
    k_attn_h<<<dim3(Sv / 128, Bv * Hv), 128, ASMEMH>>>(p_qkvh, p_ctxh);

    // 4. ao = x + ctx @ out_w^T + b  (residual fused) -> fp32
    gemm_h<<<dim3(Dv / 128, NTOK / 128), 128, GSMEMH>>>(
        p_ctxh, p_outwh, outb, p_ao, nullptr, x, Dv, Dv, Dv, Dv,
        nullptr, nullptr, nullptr, 0, 0, 0);

    // 5+6. x1 = LN1(ao) fused with gate logits/top-2; also writes x1 in fp16
    k_addln_gate<<<NTOK, 256>>>(p_ao, ln1g, ln1b, gw, gb, p_x1, p_x1h);

    // lb_loss depends only on logits: run on side stream, overlapped
    cudaEventRecord(ev_gate, 0);
    cudaStreamWaitEvent(s_side, ev_gate, 0);
    if (out_size > NTOK * Dv) {
        k_lb<<<1, 256, 0, s_side>>>(out + (size_t)NTOK * Dv);
    }
    cudaEventRecord(ev_lb, s_side);

    // 7-8. routing
    k_scan<<<1, 32>>>();
    k_assign<<<(NTOK * 2 + 255) / 256, 256>>>();

    // ---- join: w1/w2 fp16 must be ready before the MoE GEMMs
    cudaStreamWaitEvent(0, ev_join, 0);

    // 10. h = relu(gather(x1h) @ w1[e]^T + b1[e]) -> fp16 (gather fused via row_map)
    gemm_h<<<dim3(FFv / 128, MAXP / 128), 128, GSMEMH>>>(
        p_x1h, p_w1h, b1, nullptr, p_hh, nullptr, Dv, Dv, Dv, FFv,
        p_Mpad, p_off, p_gath, (long)FFv * Dv, FFv, 1);

    // 11. eo = h @ w2[e]^T + b2[e] -> fp32
    gemm_h<<<dim3(Dv / 128, MAXP / 128), 128, GSMEMH>>>(
        p_hh, p_w2h, b2, p_eo, nullptr, nullptr, FFv, FFv, FFv, Dv,
        p_Mpad, p_off, nullptr, (long)Dv * FFv, Dv, 0);

    // 12. out = LN2(x1 + moe)
    k_scatter_ln2<<<NTOK, 256>>>(p_x1, ln2g, ln2b, out);

    // rejoin side stream (lb) before capture ends
    cudaStreamWaitEvent(0, ev_lb, 0);
}